// round 7
// baseline (speedup 1.0000x reference)
#include <cuda_runtime.h>

#define NIMG 800

// ---------------- scratch (no allocation allowed) ----------------
__device__ float  g_buf1[NIMG * 4 * 30 * 30];   // conv1 pooled output (NCHW)
__device__ float  g_buf2[NIMG * 8 * 25];        // conv2 pooled output (NCHW)
__device__ float  g_z[NIMG * 2];
__device__ float  g_L[NIMG * 3];
__device__ double g_stats[24];  // [0:4) bn1 sum, [4:8) bn1 sumsq, [8:16) bn2 sum, [16:24) bn2 sumsq

__global__ void k_zero() { if (threadIdx.x < 24) g_stats[threadIdx.x] = 0.0; }

// ---- f32x2 packed-math helpers ----
__device__ __forceinline__ unsigned long long ffma2(unsigned long long a,
                                                    unsigned long long b,
                                                    unsigned long long c) {
    unsigned long long d;
    asm("fma.rn.f32x2 %0, %1, %2, %3;" : "=l"(d) : "l"(a), "l"(b), "l"(c));
    return d;
}
__device__ __forceinline__ unsigned long long packbc(float x) {  // (x, x)
    unsigned long long d;
    asm("mov.b64 %0, {%1, %2};" : "=l"(d) : "f"(x), "f"(x));
    return d;
}
__device__ __forceinline__ void unpack2(unsigned long long v, float& lo, float& hi) {
    asm("mov.b64 {%0, %1}, %2;" : "=f"(lo), "=f"(hi) : "l"(v));
}

// ---------------- conv1 + bias + relu + maxpool2 + bn1-stats ----------------
// r-outer loop: each input row loaded+packed ONCE, feeds dy=0 (kh=r) and dy=1 (kh=r-2).
__global__ __launch_bounds__(160) void k_conv1(
    const float* __restrict__ x, const float* __restrict__ cw,
    const float* __restrict__ cb)
{
    __shared__ __align__(16) float sm_in[3 * 3460];  // planar [3][27][128], plane stride 3460
    __shared__ __align__(16) float sm_w[972];        // [ic][kh][kw][oc]
    __shared__ float sm_b[4];
    __shared__ float s_part[5][8];
    const int tid = threadIdx.x;
    const int n   = blockIdx.y;
    const int r0  = blockIdx.x * 5;

    if (tid < 4) sm_b[tid] = cb[tid];
    for (int i = tid; i < 972; i += 160) {
        int oc = i & 3; int rest = i >> 2;
        int kw = rest % 9; int t2 = rest / 9; int kh = t2 % 9; int ic = t2 / 9;
        sm_w[i] = cw[oc * 243 + ic * 81 + kh * 9 + kw];
    }
    const float4* xb = (const float4*)(x + (size_t)n * 49152 + (size_t)r0 * 1536);
    for (int i = tid; i < 864; i += 160) {            // 27 rows x 32 groups
        int row = i >> 5; int g = i & 31;
        const float4* src = xb + row * 96 + g * 3;
        float4 a = src[0], b = src[1], c = src[2];
        int base = row * 128 + 4 * g;
        *(float4*)(sm_in + base)            = make_float4(a.x, a.w, b.z, c.y);
        *(float4*)(sm_in + 3460 + base)     = make_float4(a.y, b.x, b.w, c.z);
        *(float4*)(sm_in + 6920 + base)     = make_float4(a.z, b.y, c.x, c.w);
    }
    __syncthreads();

    const bool valid = (tid < 150);
    const int pw  = tid % 30;
    const int phl = valid ? (tid / 30) : 4;

    unsigned long long acc[2][2][2];   // [ocpair][dy][dx]
    #pragma unroll
    for (int p = 0; p < 2; p++)
        #pragma unroll
        for (int dy = 0; dy < 2; dy++) { acc[p][dy][0] = 0ull; acc[p][dy][1] = 0ull; }

    #pragma unroll 1
    for (int ic = 0; ic < 3; ic++) {
        const float* pl = sm_in + ic * 3460 + phl * 512 + pw * 4;
        const float* wb = sm_w + ic * 324;
        #pragma unroll
        for (int r = 0; r < 11; r++) {
            const float* rp = pl + r * 128;
            float4 va = *(const float4*)(rp);
            float4 vb = *(const float4*)(rp + 4);
            float4 vc = *(const float4*)(rp + 8);
            float in[12] = {va.x, va.y, va.z, va.w, vb.x, vb.y, vb.z, vb.w,
                            vc.x, vc.y, vc.z, vc.w};
            unsigned long long bp[11];
            #pragma unroll
            for (int j = 0; j < 11; j++) bp[j] = packbc(in[j]);
            if (r <= 8) {        // dy=0, kh=r
                #pragma unroll
                for (int kw = 0; kw < 9; kw++) {
                    ulonglong2 w2 = *(const ulonglong2*)(wb + (r * 9 + kw) * 4);
                    acc[0][0][0] = ffma2(w2.x, bp[kw],     acc[0][0][0]);
                    acc[0][0][1] = ffma2(w2.x, bp[kw + 2], acc[0][0][1]);
                    acc[1][0][0] = ffma2(w2.y, bp[kw],     acc[1][0][0]);
                    acc[1][0][1] = ffma2(w2.y, bp[kw + 2], acc[1][0][1]);
                }
            }
            if (r >= 2) {        // dy=1, kh=r-2
                #pragma unroll
                for (int kw = 0; kw < 9; kw++) {
                    ulonglong2 w2 = *(const ulonglong2*)(wb + ((r - 2) * 9 + kw) * 4);
                    acc[0][1][0] = ffma2(w2.x, bp[kw],     acc[0][1][0]);
                    acc[0][1][1] = ffma2(w2.x, bp[kw + 2], acc[0][1][1]);
                    acc[1][1][0] = ffma2(w2.y, bp[kw],     acc[1][1][0]);
                    acc[1][1][1] = ffma2(w2.y, bp[kw + 2], acc[1][1][1]);
                }
            }
        }
    }
    float m4[4];
    #pragma unroll
    for (int p = 0; p < 2; p++) {
        float l00, h00, l01, h01, l10, h10, l11, h11;
        unpack2(acc[p][0][0], l00, h00);
        unpack2(acc[p][0][1], l01, h01);
        unpack2(acc[p][1][0], l10, h10);
        unpack2(acc[p][1][1], l11, h11);
        m4[2 * p]     = fmaxf(fmaxf(l00, l01), fmaxf(l10, l11));
        m4[2 * p + 1] = fmaxf(fmaxf(h00, h01), fmaxf(h10, h11));
    }
    const int ph = r0 + phl;
    float vs[4], vq[4];
    #pragma unroll
    for (int oc = 0; oc < 4; oc++) {
        float m = fmaxf(m4[oc] + sm_b[oc], 0.f);
        if (valid) g_buf1[((n * 4 + oc) * 30 + ph) * 30 + pw] = m;
        vs[oc] = valid ? m : 0.f;
        vq[oc] = valid ? m * m : 0.f;
    }
    #pragma unroll
    for (int oc = 0; oc < 4; oc++)
        #pragma unroll
        for (int off = 16; off > 0; off >>= 1) {
            vs[oc] += __shfl_xor_sync(0xffffffffu, vs[oc], off);
            vq[oc] += __shfl_xor_sync(0xffffffffu, vq[oc], off);
        }
    const int wp = tid >> 5;
    if ((tid & 31) == 0) {
        #pragma unroll
        for (int oc = 0; oc < 4; oc++) {
            s_part[wp][oc]     = vs[oc];
            s_part[wp][4 + oc] = vq[oc];
        }
    }
    __syncthreads();
    if (tid < 8) {
        float t = 0.f;
        #pragma unroll
        for (int w = 0; w < 5; w++) t += s_part[w][tid];
        atomicAdd(&g_stats[tid], (double)t);
    }
}

// ---------------- bn1-apply + conv2 + relu + pool + bn2-stats ----------------
#define C2_IS  3844
#define C2_DSM (8 * C2_IS * 4)

__global__ __launch_bounds__(224) void k_conv2(
    const float* __restrict__ cw, const float* __restrict__ cb,
    const float* __restrict__ g1, const float* __restrict__ b1)
{
    extern __shared__ __align__(16) float c2sm[];
    __shared__ __align__(16) float sm_w[2592];   // [(ic*9+kh)*9+kw]*8 + oc
    __shared__ float sm_b[8];
    __shared__ float sc[4], shh[4];
    __shared__ float s_part[7][16];
    const int tid = threadIdx.x;
    const int n0  = blockIdx.x * 8;

    if (tid < 4) {
        double mu  = g_stats[tid] * (1.0 / 720000.0);
        double var = g_stats[4 + tid] * (1.0 / 720000.0) - mu * mu;
        float scale = g1[tid] * rsqrtf((float)var + 1e-5f);
        sc[tid] = scale; shh[tid] = b1[tid] - (float)mu * scale;
    }
    if (tid < 8) sm_b[tid] = cb[tid];
    for (int i = tid; i < 2592; i += 224) {
        int oc = i & 7; int rest = i >> 3;
        int kw = rest % 9; int t2 = rest / 9; int kh = t2 % 9; int ic = t2 / 9;
        sm_w[i] = cw[oc * 324 + ic * 81 + kh * 9 + kw];
    }
    __syncthreads();   // sc/shh ready for staging

    // independent flat-index staging (high MLP)
    for (int i = tid; i < 8 * 3600; i += 224) {
        int img = i / 3600; int rem = i - img * 3600;
        int ic  = rem / 900; int r2 = rem - ic * 900;
        int row = r2 / 30;  int col = r2 - row * 30;
        float v = fmaf(g_buf1[(size_t)(n0 + img) * 3600 + rem], sc[ic], shh[ic]);
        int chunk = col >> 2, within = col & 3;
        c2sm[img * C2_IS + ic * 960 + row * 32 + (((chunk ^ (row & 7)) << 2) | within)] = v;
    }
    __syncthreads();

    const bool valid = (tid < 200);
    const int img = valid ? (tid / 25) : 7;
    const int l25 = tid % 25;
    const int pr = l25 / 5, pc = l25 - pr * 5;

    unsigned long long acc[4][2][2];
    #pragma unroll
    for (int q = 0; q < 4; q++)
        #pragma unroll
        for (int dy = 0; dy < 2; dy++) { acc[q][dy][0] = 0ull; acc[q][dy][1] = 0ull; }

    const float* ib0 = c2sm + img * C2_IS;
    #pragma unroll 1
    for (int ic = 0; ic < 4; ic++) {
        const float* ib = ib0 + ic * 960;
        const float* wb = sm_w + ic * 648;
        #pragma unroll 1
        for (int kh = 0; kh < 9; kh++) {
            unsigned long long bpa[11], bpb[11];
            {
                int row = 4 * pr + kh;
                int rb = row * 32, rx = row & 7;
                float4 v0 = *(const float4*)(ib + rb + (((pc    ) ^ rx) << 2));
                float4 v1 = *(const float4*)(ib + rb + (((pc + 1) ^ rx) << 2));
                float4 v2 = *(const float4*)(ib + rb + (((pc + 2) ^ rx) << 2));
                float in[12] = {v0.x, v0.y, v0.z, v0.w, v1.x, v1.y, v1.z, v1.w,
                                v2.x, v2.y, v2.z, v2.w};
                #pragma unroll
                for (int j = 0; j < 11; j++) bpa[j] = packbc(in[j]);
            }
            {
                int row = 4 * pr + kh + 2;
                int rb = row * 32, rx = row & 7;
                float4 v0 = *(const float4*)(ib + rb + (((pc    ) ^ rx) << 2));
                float4 v1 = *(const float4*)(ib + rb + (((pc + 1) ^ rx) << 2));
                float4 v2 = *(const float4*)(ib + rb + (((pc + 2) ^ rx) << 2));
                float in[12] = {v0.x, v0.y, v0.z, v0.w, v1.x, v1.y, v1.z, v1.w,
                                v2.x, v2.y, v2.z, v2.w};
                #pragma unroll
                for (int j = 0; j < 11; j++) bpb[j] = packbc(in[j]);
            }
            #pragma unroll
            for (int kw = 0; kw < 9; kw++) {
                ulonglong2 wlo = *(const ulonglong2*)(wb + (kh * 9 + kw) * 8);
                ulonglong2 whi = *(const ulonglong2*)(wb + (kh * 9 + kw) * 8 + 4);
                acc[0][0][0] = ffma2(wlo.x, bpa[kw],     acc[0][0][0]);
                acc[0][0][1] = ffma2(wlo.x, bpa[kw + 2], acc[0][0][1]);
                acc[1][0][0] = ffma2(wlo.y, bpa[kw],     acc[1][0][0]);
                acc[1][0][1] = ffma2(wlo.y, bpa[kw + 2], acc[1][0][1]);
                acc[2][0][0] = ffma2(whi.x, bpa[kw],     acc[2][0][0]);
                acc[2][0][1] = ffma2(whi.x, bpa[kw + 2], acc[2][0][1]);
                acc[3][0][0] = ffma2(whi.y, bpa[kw],     acc[3][0][0]);
                acc[3][0][1] = ffma2(whi.y, bpa[kw + 2], acc[3][0][1]);
                acc[0][1][0] = ffma2(wlo.x, bpb[kw],     acc[0][1][0]);
                acc[0][1][1] = ffma2(wlo.x, bpb[kw + 2], acc[0][1][1]);
                acc[1][1][0] = ffma2(wlo.y, bpb[kw],     acc[1][1][0]);
                acc[1][1][1] = ffma2(wlo.y, bpb[kw + 2], acc[1][1][1]);
                acc[2][1][0] = ffma2(whi.x, bpb[kw],     acc[2][1][0]);
                acc[2][1][1] = ffma2(whi.x, bpb[kw + 2], acc[2][1][1]);
                acc[3][1][0] = ffma2(whi.y, bpb[kw],     acc[3][1][0]);
                acc[3][1][1] = ffma2(whi.y, bpb[kw + 2], acc[3][1][1]);
            }
        }
    }
    float vs[8], vq[8];
    #pragma unroll
    for (int q = 0; q < 4; q++) {
        float l00, h00, l01, h01, l10, h10, l11, h11;
        unpack2(acc[q][0][0], l00, h00);
        unpack2(acc[q][0][1], l01, h01);
        unpack2(acc[q][1][0], l10, h10);
        unpack2(acc[q][1][1], l11, h11);
        float mlo = fmaxf(fmaxf(l00, l01), fmaxf(l10, l11));
        float mhi = fmaxf(fmaxf(h00, h01), fmaxf(h10, h11));
        float a0 = fmaxf(mlo + sm_b[2 * q],     0.f);
        float a1 = fmaxf(mhi + sm_b[2 * q + 1], 0.f);
        if (valid) {
            g_buf2[((n0 + img) * 8 + 2 * q)     * 25 + l25] = a0;
            g_buf2[((n0 + img) * 8 + 2 * q + 1) * 25 + l25] = a1;
        }
        vs[2 * q]     = valid ? a0 : 0.f;
        vs[2 * q + 1] = valid ? a1 : 0.f;
        vq[2 * q]     = valid ? a0 * a0 : 0.f;
        vq[2 * q + 1] = valid ? a1 * a1 : 0.f;
    }
    #pragma unroll
    for (int oc = 0; oc < 8; oc++)
        #pragma unroll
        for (int off = 16; off > 0; off >>= 1) {
            vs[oc] += __shfl_xor_sync(0xffffffffu, vs[oc], off);
            vq[oc] += __shfl_xor_sync(0xffffffffu, vq[oc], off);
        }
    const int wp = tid >> 5;
    if ((tid & 31) == 0) {
        #pragma unroll
        for (int oc = 0; oc < 8; oc++) {
            s_part[wp][oc]     = vs[oc];
            s_part[wp][8 + oc] = vq[oc];
        }
    }
    __syncthreads();
    if (tid < 16) {
        float t = 0.f;
        #pragma unroll
        for (int w = 0; w < 7; w++) t += s_part[w][tid];
        atomicAdd(&g_stats[8 + tid], (double)t);
    }
}

// ---------------- bn2-apply + fc stack ----------------
__global__ __launch_bounds__(256) void k_fc(
    const float* __restrict__ W1, const float* __restrict__ b1,
    const float* __restrict__ W2, const float* __restrict__ b2,
    const float* __restrict__ Wz, const float* __restrict__ bz,
    const float* __restrict__ WL, const float* __restrict__ bL,
    const float* __restrict__ g2, const float* __restrict__ be2)
{
    __shared__ float sW1[3200], sW2[512], sWz[64], sWL[96];
    __shared__ float sb1[16], sb2[32], sbz[2], sbL[3];
    __shared__ float sc[8], shh[8];
    const int tid = threadIdx.x;
    if (tid < 8) {
        double mu  = g_stats[8 + tid] * (1.0 / 20000.0);
        double var = g_stats[16 + tid] * (1.0 / 20000.0) - mu * mu;
        float scale = g2[tid] * rsqrtf((float)var + 1e-5f);
        sc[tid] = scale; shh[tid] = be2[tid] - (float)mu * scale;
    }
    for (int i = tid; i < 3200; i += 256) sW1[i] = W1[i];
    for (int i = tid; i < 512;  i += 256) sW2[i] = W2[i];
    if (tid < 64) sWz[tid] = Wz[tid];
    if (tid < 96) sWL[tid] = WL[tid];
    if (tid < 16) sb1[tid] = b1[tid];
    if (tid < 32) sb2[tid] = b2[tid];
    if (tid < 2)  sbz[tid] = bz[tid];
    if (tid < 3)  sbL[tid] = bL[tid];
    __syncthreads();

    const int lane = tid & 31;
    const int n = blockIdx.x * 8 + (tid >> 5);
    const float* src = g_buf2 + n * 200;

    float p[16];
    #pragma unroll
    for (int i = 0; i < 16; i++) p[i] = 0.f;
    #pragma unroll
    for (int k = 0; k < 7; k++) {
        int j = lane + 32 * k;
        if (j < 200) {
            int ch = j / 25;
            float fv = fmaf(src[j], sc[ch], shh[ch]);
            #pragma unroll
            for (int i = 0; i < 16; i++) p[i] = fmaf(sW1[i * 200 + j], fv, p[i]);
        }
    }
    #pragma unroll
    for (int i = 0; i < 16; i++) {
        #pragma unroll
        for (int off = 16; off > 0; off >>= 1)
            p[i] += __shfl_xor_sync(0xffffffffu, p[i], off);
        p[i] = fmaxf(p[i] + sb1[i], 0.f);
    }
    float a = sb2[lane];
    #pragma unroll
    for (int j = 0; j < 16; j++) a = fmaf(sW2[lane * 16 + j], p[j], a);
    float f2 = fmaxf(a, 0.f);
    float v0 = sWz[lane]      * f2;
    float v1 = sWz[32 + lane] * f2;
    float v2 = sWL[lane]      * f2;
    float v3 = sWL[32 + lane] * f2;
    float v4 = sWL[64 + lane] * f2;
    #pragma unroll
    for (int off = 16; off > 0; off >>= 1) {
        v0 += __shfl_xor_sync(0xffffffffu, v0, off);
        v1 += __shfl_xor_sync(0xffffffffu, v1, off);
        v2 += __shfl_xor_sync(0xffffffffu, v2, off);
        v3 += __shfl_xor_sync(0xffffffffu, v3, off);
        v4 += __shfl_xor_sync(0xffffffffu, v4, off);
    }
    if (lane == 0) {
        g_z[n * 2]     = v0 + sbz[0];
        g_z[n * 2 + 1] = v1 + sbz[1];
        g_L[n * 3]     = v2 + sbL[0];
        g_L[n * 3 + 1] = v3 + sbL[1];
        g_L[n * 3 + 2] = v4 + sbL[2];
    }
}

// ---------------- Kalman filter: 4 lanes per sequence (row-parallel) ----------------
__global__ void k_kf(const float* __restrict__ Ag, const float* __restrict__ Bg,
                     const float* __restrict__ Cg, const float* __restrict__ Qg,
                     float* __restrict__ out)
{
    const int lane = threadIdx.x;
    if (lane >= 32) return;
    const int b   = lane >> 2;
    const int row = lane & 3;

    float A[16], C8[8], Bm[8], Q[4];
    #pragma unroll
    for (int i = 0; i < 16; i++) A[i] = Ag[i];
    #pragma unroll
    for (int i = 0; i < 8; i++)  C8[i] = Cg[i];
    #pragma unroll
    for (int i = 0; i < 8; i++)  Bm[i] = Bg[i];
    #pragma unroll
    for (int i = 0; i < 4; i++)  Q[i] = Qg[i];

    const bool cI = (C8[0] == 1.f && C8[1] == 0.f && C8[2] == 0.f && C8[3] == 0.f &&
                     C8[4] == 0.f && C8[5] == 1.f && C8[6] == 0.f && C8[7] == 0.f);

    if (cI) {
        // ---- parallel path: lane owns row `row` of the 4x4 state for sequence b ----
        float BQ[4];
        {
            float bq0 = Bm[row * 2] * Q[0] + Bm[row * 2 + 1] * Q[2];
            float bq1 = Bm[row * 2] * Q[1] + Bm[row * 2 + 1] * Q[3];
            #pragma unroll
            for (int l = 0; l < 4; l++)
                BQ[l] = bq0 * Bm[l * 2] + bq1 * Bm[l * 2 + 1];
        }
        float Ar[4] = {A[row * 4], A[row * 4 + 1], A[row * 4 + 2], A[row * 4 + 3]};
        const float* zp = g_z + b * 200;
        const float* Lp = g_L + b * 300;
        float h = (row == 0) ? zp[0] : (row == 1 ? zp[1] : 0.f);
        float l0 = Lp[0], l1 = Lp[1], l2 = Lp[2];
        float s[4];
        if (row == 0)      { s[0] = l0 * l0; s[1] = l0 * l1;            s[2] = 0.f; s[3] = 0.f; }
        else if (row == 1) { s[0] = l0 * l1; s[1] = l1 * l1 + l2 * l2;  s[2] = 0.f; s[3] = 0.f; }
        else if (row == 2) { s[0] = 0.f; s[1] = 0.f; s[2] = 1.f; s[3] = 0.f; }
        else               { s[0] = 0.f; s[1] = 0.f; s[2] = 0.f; s[3] = 1.f; }
        float* ob = out + b * 400;
        ob[row] = h;

        float nzx = zp[2], nzy = zp[3];
        float nLa = Lp[3], nLb = Lp[4], nLc = Lp[5];

        for (int t = 1; t < 100; t++) {
            float zx = nzx, zy = nzy;
            float La = nLa, Lb = nLb, Lc = nLc;
            if (t < 99) {
                nzx = zp[(t + 1) * 2];  nzy = zp[(t + 1) * 2 + 1];
                nLa = Lp[(t + 1) * 3];  nLb = Lp[(t + 1) * 3 + 1];
                nLc = Lp[(t + 1) * 3 + 2];
            }
            float r00 = La * La, r01 = La * Lb, r11 = Lb * Lb + Lc * Lc;

            // hp_row = A[row,:] @ h
            float hp = 0.f;
            #pragma unroll
            for (int k = 0; k < 4; k++)
                hp = fmaf(Ar[k], __shfl_sync(0xffffffffu, h, k, 4), hp);

            // tmp[j] = sum_k A[row,k] * s[k][j]
            float tmp[4] = {0.f, 0.f, 0.f, 0.f};
            #pragma unroll
            for (int k = 0; k < 4; k++) {
                #pragma unroll
                for (int j = 0; j < 4; j++)
                    tmp[j] = fmaf(Ar[k], __shfl_sync(0xffffffffu, s[j], k, 4), tmp[j]);
            }
            // sp[l] = BQ[l] + tmp @ A[l,:]^T
            float sp[4];
            #pragma unroll
            for (int l = 0; l < 4; l++)
                sp[l] = BQ[l] + tmp[0] * A[l * 4] + tmp[1] * A[l * 4 + 1]
                              + tmp[2] * A[l * 4 + 2] + tmp[3] * A[l * 4 + 3];

            // replicate sp rows 0,1
            float sr0[4], sr1[4];
            #pragma unroll
            for (int l = 0; l < 4; l++) {
                sr0[l] = __shfl_sync(0xffffffffu, sp[l], 0, 4);
                sr1[l] = __shfl_sync(0xffffffffu, sp[l], 1, 4);
            }
            float S00 = sr0[0] + r00, S01 = sr0[1] + r01;
            float S10 = sr1[0] + r01, S11 = sr1[1] + r11;
            float idet = 1.f / (S00 * S11 - S01 * S10);
            float Si00 = S11 * idet, Si01 = -S01 * idet;
            float Si10 = -S10 * idet, Si11 = S00 * idet;
            float K0 = sp[0] * Si00 + sp[1] * Si10;
            float K1 = sp[0] * Si01 + sp[1] * Si11;

            float hp0 = __shfl_sync(0xffffffffu, hp, 0, 4);
            float hp1 = __shfl_sync(0xffffffffu, hp, 1, 4);
            float a0 = zx - hp0, a1 = zy - hp1;
            h = hp + K0 * a0 + K1 * a1;

            #pragma unroll
            for (int l = 0; l < 4; l++)
                s[l] = sp[l] - K0 * sr0[l] - K1 * sr1[l];

            ob[t * 4 + row] = h;
        }
        return;
    }

    // ---- general-C fallback: serial per sequence (8 active lanes) ----
    if (row != 0) return;
    float BQBT[16];
    #pragma unroll
    for (int i = 0; i < 4; i++) {
        float bq0 = Bm[i * 2] * Q[0] + Bm[i * 2 + 1] * Q[2];
        float bq1 = Bm[i * 2] * Q[1] + Bm[i * 2 + 1] * Q[3];
        #pragma unroll
        for (int l = 0; l < 4; l++)
            BQBT[i * 4 + l] = bq0 * Bm[l * 2] + bq1 * Bm[l * 2 + 1];
    }
    const float* zp = g_z + b * 200;
    const float* Lp = g_L + b * 300;
    float h[4] = {zp[0], zp[1], 0.f, 0.f};
    float l0 = Lp[0], l1 = Lp[1], l2 = Lp[2];
    float s[16] = {l0 * l0, l0 * l1, 0.f, 0.f,
                   l0 * l1, l1 * l1 + l2 * l2, 0.f, 0.f,
                   0.f, 0.f, 1.f, 0.f,
                   0.f, 0.f, 0.f, 1.f};
    float* ob = out + b * 400;
    *(float4*)ob = make_float4(h[0], h[1], h[2], h[3]);

    for (int t = 1; t < 100; t++) {
        float zx = zp[t * 2], zy = zp[t * 2 + 1];
        float La = Lp[t * 3], Lb = Lp[t * 3 + 1], Lc = Lp[t * 3 + 2];
        float r00 = La * La, r01 = La * Lb, r11 = Lb * Lb + Lc * Lc;
        float hp[4];
        #pragma unroll
        for (int i = 0; i < 4; i++)
            hp[i] = A[i*4]*h[0] + A[i*4+1]*h[1] + A[i*4+2]*h[2] + A[i*4+3]*h[3];
        float tmp[16];
        #pragma unroll
        for (int i = 0; i < 4; i++)
            #pragma unroll
            for (int k = 0; k < 4; k++)
                tmp[i*4+k] = A[i*4]*s[k] + A[i*4+1]*s[4+k] + A[i*4+2]*s[8+k] + A[i*4+3]*s[12+k];
        float sp[16];
        #pragma unroll
        for (int i = 0; i < 4; i++)
            #pragma unroll
            for (int l = 0; l < 4; l++)
                sp[i*4+l] = BQBT[i*4+l] + tmp[i*4]*A[l*4] + tmp[i*4+1]*A[l*4+1]
                          + tmp[i*4+2]*A[l*4+2] + tmp[i*4+3]*A[l*4+3];
        float sct[8];
        #pragma unroll
        for (int i = 0; i < 4; i++)
            #pragma unroll
            for (int j = 0; j < 2; j++)
                sct[i*2+j] = sp[i*4]*C8[j*4] + sp[i*4+1]*C8[j*4+1]
                           + sp[i*4+2]*C8[j*4+2] + sp[i*4+3]*C8[j*4+3];
        float S00 = C8[0]*sct[0] + C8[1]*sct[2] + C8[2]*sct[4] + C8[3]*sct[6] + r00;
        float S01 = C8[0]*sct[1] + C8[1]*sct[3] + C8[2]*sct[5] + C8[3]*sct[7] + r01;
        float S10 = C8[4]*sct[0] + C8[5]*sct[2] + C8[6]*sct[4] + C8[7]*sct[6] + r01;
        float S11 = C8[4]*sct[1] + C8[5]*sct[3] + C8[6]*sct[5] + C8[7]*sct[7] + r11;
        float idet = 1.f / (S00 * S11 - S01 * S10);
        float Si00 = S11 * idet, Si01 = -S01 * idet, Si10 = -S10 * idet, Si11 = S00 * idet;
        float K[8];
        #pragma unroll
        for (int i = 0; i < 4; i++) {
            K[i*2]   = sct[i*2]*Si00 + sct[i*2+1]*Si10;
            K[i*2+1] = sct[i*2]*Si01 + sct[i*2+1]*Si11;
        }
        float a0 = zx - (C8[0]*hp[0] + C8[1]*hp[1] + C8[2]*hp[2] + C8[3]*hp[3]);
        float a1 = zy - (C8[4]*hp[0] + C8[5]*hp[1] + C8[6]*hp[2] + C8[7]*hp[3]);
        #pragma unroll
        for (int i = 0; i < 4; i++) h[i] = hp[i] + K[i*2]*a0 + K[i*2+1]*a1;
        float M[16];
        #pragma unroll
        for (int i = 0; i < 4; i++)
            #pragma unroll
            for (int j = 0; j < 4; j++)
                M[i*4+j] = (i == j ? 1.f : 0.f) - (K[i*2]*C8[j] + K[i*2+1]*C8[4+j]);
        #pragma unroll
        for (int i = 0; i < 4; i++)
            #pragma unroll
            for (int l = 0; l < 4; l++)
                s[i*4+l] = M[i*4]*sp[l] + M[i*4+1]*sp[4+l]
                         + M[i*4+2]*sp[8+l] + M[i*4+3]*sp[12+l];
        *(float4*)(ob + t * 4) = make_float4(h[0], h[1], h[2], h[3]);
    }
}

extern "C" void kernel_launch(void* const* d_in, const int* in_sizes, int n_in,
                              void* d_out, int out_size) {
    const float* x    = (const float*)d_in[0];
    const float* c1w  = (const float*)d_in[1];
    const float* c1b  = (const float*)d_in[2];
    const float* bn1g = (const float*)d_in[3];
    const float* bn1b = (const float*)d_in[4];
    const float* c2w  = (const float*)d_in[5];
    const float* c2b  = (const float*)d_in[6];
    const float* bn2g = (const float*)d_in[7];
    const float* bn2b = (const float*)d_in[8];
    const float* W1   = (const float*)d_in[9];
    const float* b1   = (const float*)d_in[10];
    const float* W2   = (const float*)d_in[11];
    const float* b2   = (const float*)d_in[12];
    const float* Wz   = (const float*)d_in[13];
    const float* bz   = (const float*)d_in[14];
    const float* WL   = (const float*)d_in[15];
    const float* bL   = (const float*)d_in[16];
    const float* A    = (const float*)d_in[17];
    const float* B    = (const float*)d_in[18];
    const float* C    = (const float*)d_in[19];
    const float* Q    = (const float*)d_in[20];
    float* out = (float*)d_out;

    static int attr_done = 0;
    if (!attr_done) {
        cudaFuncSetAttribute(k_conv2, cudaFuncAttributeMaxDynamicSharedMemorySize, C2_DSM);
        attr_done = 1;
    }

    k_zero<<<1, 32>>>();
    k_conv1<<<dim3(6, 800), 160>>>(x, c1w, c1b);
    k_conv2<<<100, 224, C2_DSM>>>(c2w, c2b, bn1g, bn1b);
    k_fc<<<100, 256>>>(W1, b1, W2, b2, Wz, bz, WL, bL, bn2g, bn2b);
    k_kf<<<1, 32>>>(A, B, C, Q, out);
}

// round 8
// speedup vs baseline: 1.0460x; 1.0460x over previous
#include <cuda_runtime.h>

#define NIMG 800

// ---------------- scratch (no allocation allowed) ----------------
__device__ float  g_buf1[NIMG * 4 * 30 * 30];   // conv1 pooled output (NCHW)
__device__ float  g_buf2[NIMG * 8 * 25];        // conv2 pooled output (NCHW)
__device__ float  g_z[NIMG * 2];
__device__ float  g_L[NIMG * 3];
__device__ double g_stats[24];  // [0:4) bn1 sum, [4:8) bn1 sumsq, [8:16) bn2 sum, [16:24) bn2 sumsq

__global__ void k_zero() { if (threadIdx.x < 24) g_stats[threadIdx.x] = 0.0; }

// ---- f32x2 packed-math helpers ----
__device__ __forceinline__ unsigned long long ffma2(unsigned long long a,
                                                    unsigned long long b,
                                                    unsigned long long c) {
    unsigned long long d;
    asm("fma.rn.f32x2 %0, %1, %2, %3;" : "=l"(d) : "l"(a), "l"(b), "l"(c));
    return d;
}
__device__ __forceinline__ unsigned long long packbc(float x) {  // (x, x)
    unsigned long long d;
    asm("mov.b64 %0, {%1, %2};" : "=l"(d) : "f"(x), "f"(x));
    return d;
}
__device__ __forceinline__ void unpack2(unsigned long long v, float& lo, float& hi) {
    asm("mov.b64 {%0, %1}, %2;" : "=f"(lo), "=f"(hi) : "l"(v));
}

// load one input row (12 floats via 3x LDS.128) and broadcast-pack 11 windows
__device__ __forceinline__ void c1_load_row(const float* rp, unsigned long long bp[11]) {
    float4 va = *(const float4*)(rp);
    float4 vb = *(const float4*)(rp + 4);
    float4 vc = *(const float4*)(rp + 8);
    float in[12] = {va.x, va.y, va.z, va.w, vb.x, vb.y, vb.z, vb.w,
                    vc.x, vc.y, vc.z, vc.w};
    #pragma unroll
    for (int j = 0; j < 11; j++) bp[j] = packbc(in[j]);
}

// one kh slice: weights w[kh] applied to rowLow (dy=0, row kh) and rowHigh (dy=1, row kh+2)
__device__ __forceinline__ void c1_fma_kh(const float* wb, int kh,
                                          const unsigned long long rl[11],
                                          const unsigned long long rh[11],
                                          unsigned long long acc[2][2][2]) {
    #pragma unroll
    for (int kw = 0; kw < 9; kw++) {
        ulonglong2 w2 = *(const ulonglong2*)(wb + (kh * 9 + kw) * 4);
        acc[0][0][0] = ffma2(w2.x, rl[kw],     acc[0][0][0]);
        acc[0][0][1] = ffma2(w2.x, rl[kw + 2], acc[0][0][1]);
        acc[1][0][0] = ffma2(w2.y, rl[kw],     acc[1][0][0]);
        acc[1][0][1] = ffma2(w2.y, rl[kw + 2], acc[1][0][1]);
        acc[0][1][0] = ffma2(w2.x, rh[kw],     acc[0][1][0]);
        acc[0][1][1] = ffma2(w2.x, rh[kw + 2], acc[0][1][1]);
        acc[1][1][0] = ffma2(w2.y, rh[kw],     acc[1][1][0]);
        acc[1][1][1] = ffma2(w2.y, rh[kw + 2], acc[1][1][1]);
    }
}

// ---------------- conv1 + bias + relu + maxpool2 + bn1-stats ----------------
// kh-ordered weights (each loaded once) + parity-chain double-buffered rows (each loaded once).
__global__ __launch_bounds__(160) void k_conv1(
    const float* __restrict__ x, const float* __restrict__ cw,
    const float* __restrict__ cb)
{
    __shared__ __align__(16) float sm_in[3 * 3460];  // planar [3][27][128], plane stride 3460
    __shared__ __align__(16) float sm_w[972];        // [ic][kh][kw][oc]
    __shared__ float sm_b[4];
    __shared__ float s_part[5][8];
    const int tid = threadIdx.x;
    const int n   = blockIdx.y;
    const int r0  = blockIdx.x * 5;

    if (tid < 4) sm_b[tid] = cb[tid];
    for (int i = tid; i < 972; i += 160) {
        int oc = i & 3; int rest = i >> 2;
        int kw = rest % 9; int t2 = rest / 9; int kh = t2 % 9; int ic = t2 / 9;
        sm_w[i] = cw[oc * 243 + ic * 81 + kh * 9 + kw];
    }
    const float4* xb = (const float4*)(x + (size_t)n * 49152 + (size_t)r0 * 1536);
    for (int i = tid; i < 864; i += 160) {            // 27 rows x 32 groups
        int row = i >> 5; int g = i & 31;
        const float4* src = xb + row * 96 + g * 3;
        float4 a = src[0], b = src[1], c = src[2];
        int base = row * 128 + 4 * g;
        *(float4*)(sm_in + base)            = make_float4(a.x, a.w, b.z, c.y);
        *(float4*)(sm_in + 3460 + base)     = make_float4(a.y, b.x, b.w, c.z);
        *(float4*)(sm_in + 6920 + base)     = make_float4(a.z, b.y, c.x, c.w);
    }
    __syncthreads();

    const bool valid = (tid < 150);
    const int pw  = tid % 30;
    const int phl = valid ? (tid / 30) : 4;

    unsigned long long acc[2][2][2];   // [ocpair][dy][dx]
    #pragma unroll
    for (int p = 0; p < 2; p++)
        #pragma unroll
        for (int dy = 0; dy < 2; dy++) { acc[p][dy][0] = 0ull; acc[p][dy][1] = 0ull; }

    #pragma unroll 1
    for (int ic = 0; ic < 3; ic++) {
        const float* pl = sm_in + ic * 3460 + phl * 512 + pw * 4;
        const float* wb = sm_w + ic * 324;
        unsigned long long ra[11], rb[11];
        // even chain: kh = 0,2,4,6,8 (rows 0,2,4,6,8,10 — each loaded once)
        c1_load_row(pl, ra);
        c1_load_row(pl + 2 * 128, rb);
        c1_fma_kh(wb, 0, ra, rb, acc);
        c1_load_row(pl + 4 * 128, ra);
        c1_fma_kh(wb, 2, rb, ra, acc);
        c1_load_row(pl + 6 * 128, rb);
        c1_fma_kh(wb, 4, ra, rb, acc);
        c1_load_row(pl + 8 * 128, ra);
        c1_fma_kh(wb, 6, rb, ra, acc);
        c1_load_row(pl + 10 * 128, rb);
        c1_fma_kh(wb, 8, ra, rb, acc);
        // odd chain: kh = 1,3,5,7 (rows 1,3,5,7,9 — each loaded once)
        c1_load_row(pl + 1 * 128, ra);
        c1_load_row(pl + 3 * 128, rb);
        c1_fma_kh(wb, 1, ra, rb, acc);
        c1_load_row(pl + 5 * 128, ra);
        c1_fma_kh(wb, 3, rb, ra, acc);
        c1_load_row(pl + 7 * 128, rb);
        c1_fma_kh(wb, 5, ra, rb, acc);
        c1_load_row(pl + 9 * 128, ra);
        c1_fma_kh(wb, 7, rb, ra, acc);
    }
    float m4[4];
    #pragma unroll
    for (int p = 0; p < 2; p++) {
        float l00, h00, l01, h01, l10, h10, l11, h11;
        unpack2(acc[p][0][0], l00, h00);
        unpack2(acc[p][0][1], l01, h01);
        unpack2(acc[p][1][0], l10, h10);
        unpack2(acc[p][1][1], l11, h11);
        m4[2 * p]     = fmaxf(fmaxf(l00, l01), fmaxf(l10, l11));
        m4[2 * p + 1] = fmaxf(fmaxf(h00, h01), fmaxf(h10, h11));
    }
    const int ph = r0 + phl;
    float vs[4], vq[4];
    #pragma unroll
    for (int oc = 0; oc < 4; oc++) {
        float m = fmaxf(m4[oc] + sm_b[oc], 0.f);
        if (valid) g_buf1[((n * 4 + oc) * 30 + ph) * 30 + pw] = m;
        vs[oc] = valid ? m : 0.f;
        vq[oc] = valid ? m * m : 0.f;
    }
    #pragma unroll
    for (int oc = 0; oc < 4; oc++)
        #pragma unroll
        for (int off = 16; off > 0; off >>= 1) {
            vs[oc] += __shfl_xor_sync(0xffffffffu, vs[oc], off);
            vq[oc] += __shfl_xor_sync(0xffffffffu, vq[oc], off);
        }
    const int wp = tid >> 5;
    if ((tid & 31) == 0) {
        #pragma unroll
        for (int oc = 0; oc < 4; oc++) {
            s_part[wp][oc]     = vs[oc];
            s_part[wp][4 + oc] = vq[oc];
        }
    }
    __syncthreads();
    if (tid < 8) {
        float t = 0.f;
        #pragma unroll
        for (int w = 0; w < 5; w++) t += s_part[w][tid];
        atomicAdd(&g_stats[tid], (double)t);
    }
}

// ---------------- bn1-apply + conv2 + relu + pool + bn2-stats ----------------
#define C2_IS  3844
#define C2_DSM (8 * C2_IS * 4)

__global__ __launch_bounds__(224) void k_conv2(
    const float* __restrict__ cw, const float* __restrict__ cb,
    const float* __restrict__ g1, const float* __restrict__ b1)
{
    extern __shared__ __align__(16) float c2sm[];
    __shared__ __align__(16) float sm_w[2592];   // [(ic*9+kh)*9+kw]*8 + oc
    __shared__ float sm_b[8];
    __shared__ float sc[4], shh[4];
    __shared__ float s_part[7][16];
    const int tid = threadIdx.x;
    const int n0  = blockIdx.x * 8;

    if (tid < 4) {
        double mu  = g_stats[tid] * (1.0 / 720000.0);
        double var = g_stats[4 + tid] * (1.0 / 720000.0) - mu * mu;
        float scale = g1[tid] * rsqrtf((float)var + 1e-5f);
        sc[tid] = scale; shh[tid] = b1[tid] - (float)mu * scale;
    }
    if (tid < 8) sm_b[tid] = cb[tid];
    for (int i = tid; i < 2592; i += 224) {
        int oc = i & 7; int rest = i >> 3;
        int kw = rest % 9; int t2 = rest / 9; int kh = t2 % 9; int ic = t2 / 9;
        sm_w[i] = cw[oc * 324 + ic * 81 + kh * 9 + kw];
    }
    __syncthreads();   // sc/shh ready for staging

    // independent flat-index staging (high MLP)
    for (int i = tid; i < 8 * 3600; i += 224) {
        int img = i / 3600; int rem = i - img * 3600;
        int ic  = rem / 900; int r2 = rem - ic * 900;
        int row = r2 / 30;  int col = r2 - row * 30;
        float v = fmaf(g_buf1[(size_t)(n0 + img) * 3600 + rem], sc[ic], shh[ic]);
        int chunk = col >> 2, within = col & 3;
        c2sm[img * C2_IS + ic * 960 + row * 32 + (((chunk ^ (row & 7)) << 2) | within)] = v;
    }
    __syncthreads();

    const bool valid = (tid < 200);
    const int img = valid ? (tid / 25) : 7;
    const int l25 = tid % 25;
    const int pr = l25 / 5, pc = l25 - pr * 5;

    unsigned long long acc[4][2][2];
    #pragma unroll
    for (int q = 0; q < 4; q++)
        #pragma unroll
        for (int dy = 0; dy < 2; dy++) { acc[q][dy][0] = 0ull; acc[q][dy][1] = 0ull; }

    const float* ib0 = c2sm + img * C2_IS;
    #pragma unroll 1
    for (int ic = 0; ic < 4; ic++) {
        const float* ib = ib0 + ic * 960;
        const float* wb = sm_w + ic * 648;
        #pragma unroll 1
        for (int kh = 0; kh < 9; kh++) {
            unsigned long long bpa[11], bpb[11];
            {
                int row = 4 * pr + kh;
                int rb = row * 32, rx = row & 7;
                float4 v0 = *(const float4*)(ib + rb + (((pc    ) ^ rx) << 2));
                float4 v1 = *(const float4*)(ib + rb + (((pc + 1) ^ rx) << 2));
                float4 v2 = *(const float4*)(ib + rb + (((pc + 2) ^ rx) << 2));
                float in[12] = {v0.x, v0.y, v0.z, v0.w, v1.x, v1.y, v1.z, v1.w,
                                v2.x, v2.y, v2.z, v2.w};
                #pragma unroll
                for (int j = 0; j < 11; j++) bpa[j] = packbc(in[j]);
            }
            {
                int row = 4 * pr + kh + 2;
                int rb = row * 32, rx = row & 7;
                float4 v0 = *(const float4*)(ib + rb + (((pc    ) ^ rx) << 2));
                float4 v1 = *(const float4*)(ib + rb + (((pc + 1) ^ rx) << 2));
                float4 v2 = *(const float4*)(ib + rb + (((pc + 2) ^ rx) << 2));
                float in[12] = {v0.x, v0.y, v0.z, v0.w, v1.x, v1.y, v1.z, v1.w,
                                v2.x, v2.y, v2.z, v2.w};
                #pragma unroll
                for (int j = 0; j < 11; j++) bpb[j] = packbc(in[j]);
            }
            #pragma unroll
            for (int kw = 0; kw < 9; kw++) {
                ulonglong2 wlo = *(const ulonglong2*)(wb + (kh * 9 + kw) * 8);
                ulonglong2 whi = *(const ulonglong2*)(wb + (kh * 9 + kw) * 8 + 4);
                acc[0][0][0] = ffma2(wlo.x, bpa[kw],     acc[0][0][0]);
                acc[0][0][1] = ffma2(wlo.x, bpa[kw + 2], acc[0][0][1]);
                acc[1][0][0] = ffma2(wlo.y, bpa[kw],     acc[1][0][0]);
                acc[1][0][1] = ffma2(wlo.y, bpa[kw + 2], acc[1][0][1]);
                acc[2][0][0] = ffma2(whi.x, bpa[kw],     acc[2][0][0]);
                acc[2][0][1] = ffma2(whi.x, bpa[kw + 2], acc[2][0][1]);
                acc[3][0][0] = ffma2(whi.y, bpa[kw],     acc[3][0][0]);
                acc[3][0][1] = ffma2(whi.y, bpa[kw + 2], acc[3][0][1]);
                acc[0][1][0] = ffma2(wlo.x, bpb[kw],     acc[0][1][0]);
                acc[0][1][1] = ffma2(wlo.x, bpb[kw + 2], acc[0][1][1]);
                acc[1][1][0] = ffma2(wlo.y, bpb[kw],     acc[1][1][0]);
                acc[1][1][1] = ffma2(wlo.y, bpb[kw + 2], acc[1][1][1]);
                acc[2][1][0] = ffma2(whi.x, bpb[kw],     acc[2][1][0]);
                acc[2][1][1] = ffma2(whi.x, bpb[kw + 2], acc[2][1][1]);
                acc[3][1][0] = ffma2(whi.y, bpb[kw],     acc[3][1][0]);
                acc[3][1][1] = ffma2(whi.y, bpb[kw + 2], acc[3][1][1]);
            }
        }
    }
    float vs[8], vq[8];
    #pragma unroll
    for (int q = 0; q < 4; q++) {
        float l00, h00, l01, h01, l10, h10, l11, h11;
        unpack2(acc[q][0][0], l00, h00);
        unpack2(acc[q][0][1], l01, h01);
        unpack2(acc[q][1][0], l10, h10);
        unpack2(acc[q][1][1], l11, h11);
        float mlo = fmaxf(fmaxf(l00, l01), fmaxf(l10, l11));
        float mhi = fmaxf(fmaxf(h00, h01), fmaxf(h10, h11));
        float a0 = fmaxf(mlo + sm_b[2 * q],     0.f);
        float a1 = fmaxf(mhi + sm_b[2 * q + 1], 0.f);
        if (valid) {
            g_buf2[((n0 + img) * 8 + 2 * q)     * 25 + l25] = a0;
            g_buf2[((n0 + img) * 8 + 2 * q + 1) * 25 + l25] = a1;
        }
        vs[2 * q]     = valid ? a0 : 0.f;
        vs[2 * q + 1] = valid ? a1 : 0.f;
        vq[2 * q]     = valid ? a0 * a0 : 0.f;
        vq[2 * q + 1] = valid ? a1 * a1 : 0.f;
    }
    #pragma unroll
    for (int oc = 0; oc < 8; oc++)
        #pragma unroll
        for (int off = 16; off > 0; off >>= 1) {
            vs[oc] += __shfl_xor_sync(0xffffffffu, vs[oc], off);
            vq[oc] += __shfl_xor_sync(0xffffffffu, vq[oc], off);
        }
    const int wp = tid >> 5;
    if ((tid & 31) == 0) {
        #pragma unroll
        for (int oc = 0; oc < 8; oc++) {
            s_part[wp][oc]     = vs[oc];
            s_part[wp][8 + oc] = vq[oc];
        }
    }
    __syncthreads();
    if (tid < 16) {
        float t = 0.f;
        #pragma unroll
        for (int w = 0; w < 7; w++) t += s_part[w][tid];
        atomicAdd(&g_stats[8 + tid], (double)t);
    }
}

// ---------------- bn2-apply + fc stack ----------------
__global__ __launch_bounds__(256) void k_fc(
    const float* __restrict__ W1, const float* __restrict__ b1,
    const float* __restrict__ W2, const float* __restrict__ b2,
    const float* __restrict__ Wz, const float* __restrict__ bz,
    const float* __restrict__ WL, const float* __restrict__ bL,
    const float* __restrict__ g2, const float* __restrict__ be2)
{
    __shared__ float sW1[3200], sW2[512], sWz[64], sWL[96];
    __shared__ float sb1[16], sb2[32], sbz[2], sbL[3];
    __shared__ float sc[8], shh[8];
    const int tid = threadIdx.x;
    if (tid < 8) {
        double mu  = g_stats[8 + tid] * (1.0 / 20000.0);
        double var = g_stats[16 + tid] * (1.0 / 20000.0) - mu * mu;
        float scale = g2[tid] * rsqrtf((float)var + 1e-5f);
        sc[tid] = scale; shh[tid] = be2[tid] - (float)mu * scale;
    }
    for (int i = tid; i < 3200; i += 256) sW1[i] = W1[i];
    for (int i = tid; i < 512;  i += 256) sW2[i] = W2[i];
    if (tid < 64) sWz[tid] = Wz[tid];
    if (tid < 96) sWL[tid] = WL[tid];
    if (tid < 16) sb1[tid] = b1[tid];
    if (tid < 32) sb2[tid] = b2[tid];
    if (tid < 2)  sbz[tid] = bz[tid];
    if (tid < 3)  sbL[tid] = bL[tid];
    __syncthreads();

    const int lane = tid & 31;
    const int n = blockIdx.x * 8 + (tid >> 5);
    const float* src = g_buf2 + n * 200;

    float p[16];
    #pragma unroll
    for (int i = 0; i < 16; i++) p[i] = 0.f;
    #pragma unroll
    for (int k = 0; k < 7; k++) {
        int j = lane + 32 * k;
        if (j < 200) {
            int ch = j / 25;
            float fv = fmaf(src[j], sc[ch], shh[ch]);
            #pragma unroll
            for (int i = 0; i < 16; i++) p[i] = fmaf(sW1[i * 200 + j], fv, p[i]);
        }
    }
    #pragma unroll
    for (int i = 0; i < 16; i++) {
        #pragma unroll
        for (int off = 16; off > 0; off >>= 1)
            p[i] += __shfl_xor_sync(0xffffffffu, p[i], off);
        p[i] = fmaxf(p[i] + sb1[i], 0.f);
    }
    float a = sb2[lane];
    #pragma unroll
    for (int j = 0; j < 16; j++) a = fmaf(sW2[lane * 16 + j], p[j], a);
    float f2 = fmaxf(a, 0.f);
    float v0 = sWz[lane]      * f2;
    float v1 = sWz[32 + lane] * f2;
    float v2 = sWL[lane]      * f2;
    float v3 = sWL[32 + lane] * f2;
    float v4 = sWL[64 + lane] * f2;
    #pragma unroll
    for (int off = 16; off > 0; off >>= 1) {
        v0 += __shfl_xor_sync(0xffffffffu, v0, off);
        v1 += __shfl_xor_sync(0xffffffffu, v1, off);
        v2 += __shfl_xor_sync(0xffffffffu, v2, off);
        v3 += __shfl_xor_sync(0xffffffffu, v3, off);
        v4 += __shfl_xor_sync(0xffffffffu, v4, off);
    }
    if (lane == 0) {
        g_z[n * 2]     = v0 + sbz[0];
        g_z[n * 2 + 1] = v1 + sbz[1];
        g_L[n * 3]     = v2 + sbL[0];
        g_L[n * 3 + 1] = v3 + sbL[1];
        g_L[n * 3 + 2] = v4 + sbL[2];
    }
}

// ---------------- Kalman filter: 4 lanes per sequence (row-parallel) ----------------
__global__ void k_kf(const float* __restrict__ Ag, const float* __restrict__ Bg,
                     const float* __restrict__ Cg, const float* __restrict__ Qg,
                     float* __restrict__ out)
{
    const int lane = threadIdx.x;
    if (lane >= 32) return;
    const int b   = lane >> 2;
    const int row = lane & 3;

    float A[16], C8[8], Bm[8], Q[4];
    #pragma unroll
    for (int i = 0; i < 16; i++) A[i] = Ag[i];
    #pragma unroll
    for (int i = 0; i < 8; i++)  C8[i] = Cg[i];
    #pragma unroll
    for (int i = 0; i < 8; i++)  Bm[i] = Bg[i];
    #pragma unroll
    for (int i = 0; i < 4; i++)  Q[i] = Qg[i];

    const bool cI = (C8[0] == 1.f && C8[1] == 0.f && C8[2] == 0.f && C8[3] == 0.f &&
                     C8[4] == 0.f && C8[5] == 1.f && C8[6] == 0.f && C8[7] == 0.f);

    if (cI) {
        float BQ[4];
        {
            float bq0 = Bm[row * 2] * Q[0] + Bm[row * 2 + 1] * Q[2];
            float bq1 = Bm[row * 2] * Q[1] + Bm[row * 2 + 1] * Q[3];
            #pragma unroll
            for (int l = 0; l < 4; l++)
                BQ[l] = bq0 * Bm[l * 2] + bq1 * Bm[l * 2 + 1];
        }
        float Ar[4] = {A[row * 4], A[row * 4 + 1], A[row * 4 + 2], A[row * 4 + 3]};
        const float* zp = g_z + b * 200;
        const float* Lp = g_L + b * 300;
        float h = (row == 0) ? zp[0] : (row == 1 ? zp[1] : 0.f);
        float l0 = Lp[0], l1 = Lp[1], l2 = Lp[2];
        float s[4];
        if (row == 0)      { s[0] = l0 * l0; s[1] = l0 * l1;            s[2] = 0.f; s[3] = 0.f; }
        else if (row == 1) { s[0] = l0 * l1; s[1] = l1 * l1 + l2 * l2;  s[2] = 0.f; s[3] = 0.f; }
        else if (row == 2) { s[0] = 0.f; s[1] = 0.f; s[2] = 1.f; s[3] = 0.f; }
        else               { s[0] = 0.f; s[1] = 0.f; s[2] = 0.f; s[3] = 1.f; }
        float* ob = out + b * 400;
        ob[row] = h;

        float nzx = zp[2], nzy = zp[3];
        float nLa = Lp[3], nLb = Lp[4], nLc = Lp[5];

        for (int t = 1; t < 100; t++) {
            float zx = nzx, zy = nzy;
            float La = nLa, Lb = nLb, Lc = nLc;
            if (t < 99) {
                nzx = zp[(t + 1) * 2];  nzy = zp[(t + 1) * 2 + 1];
                nLa = Lp[(t + 1) * 3];  nLb = Lp[(t + 1) * 3 + 1];
                nLc = Lp[(t + 1) * 3 + 2];
            }
            float r00 = La * La, r01 = La * Lb, r11 = Lb * Lb + Lc * Lc;

            float hp = 0.f;
            #pragma unroll
            for (int k = 0; k < 4; k++)
                hp = fmaf(Ar[k], __shfl_sync(0xffffffffu, h, k, 4), hp);

            float tmp[4] = {0.f, 0.f, 0.f, 0.f};
            #pragma unroll
            for (int k = 0; k < 4; k++) {
                #pragma unroll
                for (int j = 0; j < 4; j++)
                    tmp[j] = fmaf(Ar[k], __shfl_sync(0xffffffffu, s[j], k, 4), tmp[j]);
            }
            float sp[4];
            #pragma unroll
            for (int l = 0; l < 4; l++)
                sp[l] = BQ[l] + tmp[0] * A[l * 4] + tmp[1] * A[l * 4 + 1]
                              + tmp[2] * A[l * 4 + 2] + tmp[3] * A[l * 4 + 3];

            float sr0[4], sr1[4];
            #pragma unroll
            for (int l = 0; l < 4; l++) {
                sr0[l] = __shfl_sync(0xffffffffu, sp[l], 0, 4);
                sr1[l] = __shfl_sync(0xffffffffu, sp[l], 1, 4);
            }
            float S00 = sr0[0] + r00, S01 = sr0[1] + r01;
            float S10 = sr1[0] + r01, S11 = sr1[1] + r11;
            float idet = 1.f / (S00 * S11 - S01 * S10);
            float Si00 = S11 * idet, Si01 = -S01 * idet;
            float Si10 = -S10 * idet, Si11 = S00 * idet;
            float K0 = sp[0] * Si00 + sp[1] * Si10;
            float K1 = sp[0] * Si01 + sp[1] * Si11;

            float hp0 = __shfl_sync(0xffffffffu, hp, 0, 4);
            float hp1 = __shfl_sync(0xffffffffu, hp, 1, 4);
            float a0 = zx - hp0, a1 = zy - hp1;
            h = hp + K0 * a0 + K1 * a1;

            #pragma unroll
            for (int l = 0; l < 4; l++)
                s[l] = sp[l] - K0 * sr0[l] - K1 * sr1[l];

            ob[t * 4 + row] = h;
        }
        return;
    }

    // ---- general-C fallback: serial per sequence (8 active lanes) ----
    if (row != 0) return;
    float BQBT[16];
    #pragma unroll
    for (int i = 0; i < 4; i++) {
        float bq0 = Bm[i * 2] * Q[0] + Bm[i * 2 + 1] * Q[2];
        float bq1 = Bm[i * 2] * Q[1] + Bm[i * 2 + 1] * Q[3];
        #pragma unroll
        for (int l = 0; l < 4; l++)
            BQBT[i * 4 + l] = bq0 * Bm[l * 2] + bq1 * Bm[l * 2 + 1];
    }
    const float* zp = g_z + b * 200;
    const float* Lp = g_L + b * 300;
    float h[4] = {zp[0], zp[1], 0.f, 0.f};
    float l0 = Lp[0], l1 = Lp[1], l2 = Lp[2];
    float s[16] = {l0 * l0, l0 * l1, 0.f, 0.f,
                   l0 * l1, l1 * l1 + l2 * l2, 0.f, 0.f,
                   0.f, 0.f, 1.f, 0.f,
                   0.f, 0.f, 0.f, 1.f};
    float* ob = out + b * 400;
    *(float4*)ob = make_float4(h[0], h[1], h[2], h[3]);

    for (int t = 1; t < 100; t++) {
        float zx = zp[t * 2], zy = zp[t * 2 + 1];
        float La = Lp[t * 3], Lb = Lp[t * 3 + 1], Lc = Lp[t * 3 + 2];
        float r00 = La * La, r01 = La * Lb, r11 = Lb * Lb + Lc * Lc;
        float hp[4];
        #pragma unroll
        for (int i = 0; i < 4; i++)
            hp[i] = A[i*4]*h[0] + A[i*4+1]*h[1] + A[i*4+2]*h[2] + A[i*4+3]*h[3];
        float tmp[16];
        #pragma unroll
        for (int i = 0; i < 4; i++)
            #pragma unroll
            for (int k = 0; k < 4; k++)
                tmp[i*4+k] = A[i*4]*s[k] + A[i*4+1]*s[4+k] + A[i*4+2]*s[8+k] + A[i*4+3]*s[12+k];
        float sp[16];
        #pragma unroll
        for (int i = 0; i < 4; i++)
            #pragma unroll
            for (int l = 0; l < 4; l++)
                sp[i*4+l] = BQBT[i*4+l] + tmp[i*4]*A[l*4] + tmp[i*4+1]*A[l*4+1]
                          + tmp[i*4+2]*A[l*4+2] + tmp[i*4+3]*A[l*4+3];
        float sct[8];
        #pragma unroll
        for (int i = 0; i < 4; i++)
            #pragma unroll
            for (int j = 0; j < 2; j++)
                sct[i*2+j] = sp[i*4]*C8[j*4] + sp[i*4+1]*C8[j*4+1]
                           + sp[i*4+2]*C8[j*4+2] + sp[i*4+3]*C8[j*4+3];
        float S00 = C8[0]*sct[0] + C8[1]*sct[2] + C8[2]*sct[4] + C8[3]*sct[6] + r00;
        float S01 = C8[0]*sct[1] + C8[1]*sct[3] + C8[2]*sct[5] + C8[3]*sct[7] + r01;
        float S10 = C8[4]*sct[0] + C8[5]*sct[2] + C8[6]*sct[4] + C8[7]*sct[6] + r01;
        float S11 = C8[4]*sct[1] + C8[5]*sct[3] + C8[6]*sct[5] + C8[7]*sct[7] + r11;
        float idet = 1.f / (S00 * S11 - S01 * S10);
        float Si00 = S11 * idet, Si01 = -S01 * idet, Si10 = -S10 * idet, Si11 = S00 * idet;
        float K[8];
        #pragma unroll
        for (int i = 0; i < 4; i++) {
            K[i*2]   = sct[i*2]*Si00 + sct[i*2+1]*Si10;
            K[i*2+1] = sct[i*2]*Si01 + sct[i*2+1]*Si11;
        }
        float a0 = zx - (C8[0]*hp[0] + C8[1]*hp[1] + C8[2]*hp[2] + C8[3]*hp[3]);
        float a1 = zy - (C8[4]*hp[0] + C8[5]*hp[1] + C8[6]*hp[2] + C8[7]*hp[3]);
        #pragma unroll
        for (int i = 0; i < 4; i++) h[i] = hp[i] + K[i*2]*a0 + K[i*2+1]*a1;
        float M[16];
        #pragma unroll
        for (int i = 0; i < 4; i++)
            #pragma unroll
            for (int j = 0; j < 4; j++)
                M[i*4+j] = (i == j ? 1.f : 0.f) - (K[i*2]*C8[j] + K[i*2+1]*C8[4+j]);
        #pragma unroll
        for (int i = 0; i < 4; i++)
            #pragma unroll
            for (int l = 0; l < 4; l++)
                s[i*4+l] = M[i*4]*sp[l] + M[i*4+1]*sp[4+l]
                         + M[i*4+2]*sp[8+l] + M[i*4+3]*sp[12+l];
        *(float4*)(ob + t * 4) = make_float4(h[0], h[1], h[2], h[3]);
    }
}

extern "C" void kernel_launch(void* const* d_in, const int* in_sizes, int n_in,
                              void* d_out, int out_size) {
    const float* x    = (const float*)d_in[0];
    const float* c1w  = (const float*)d_in[1];
    const float* c1b  = (const float*)d_in[2];
    const float* bn1g = (const float*)d_in[3];
    const float* bn1b = (const float*)d_in[4];
    const float* c2w  = (const float*)d_in[5];
    const float* c2b  = (const float*)d_in[6];
    const float* bn2g = (const float*)d_in[7];
    const float* bn2b = (const float*)d_in[8];
    const float* W1   = (const float*)d_in[9];
    const float* b1   = (const float*)d_in[10];
    const float* W2   = (const float*)d_in[11];
    const float* b2   = (const float*)d_in[12];
    const float* Wz   = (const float*)d_in[13];
    const float* bz   = (const float*)d_in[14];
    const float* WL   = (const float*)d_in[15];
    const float* bL   = (const float*)d_in[16];
    const float* A    = (const float*)d_in[17];
    const float* B    = (const float*)d_in[18];
    const float* C    = (const float*)d_in[19];
    const float* Q    = (const float*)d_in[20];
    float* out = (float*)d_out;

    static int attr_done = 0;
    if (!attr_done) {
        cudaFuncSetAttribute(k_conv2, cudaFuncAttributeMaxDynamicSharedMemorySize, C2_DSM);
        attr_done = 1;
    }

    k_zero<<<1, 32>>>();
    k_conv1<<<dim3(6, 800), 160>>>(x, c1w, c1b);
    k_conv2<<<100, 224, C2_DSM>>>(c2w, c2b, bn1g, bn1b);
    k_fc<<<100, 256>>>(W1, b1, W2, b2, Wz, bz, WL, bL, bn2g, bn2b);
    k_kf<<<1, 32>>>(A, B, C, Q, out);
}

// round 10
// speedup vs baseline: 1.0586x; 1.0120x over previous
#include <cuda_runtime.h>

#define NIMG 800

// ---------------- scratch (no allocation allowed) ----------------
__device__ float  g_buf1[NIMG * 4 * 30 * 30];   // conv1 pooled output (NCHW)
__device__ float  g_buf2[NIMG * 8 * 25];        // conv2 pooled output (NCHW)
__device__ float  g_z[NIMG * 2];
__device__ float  g_L[NIMG * 3];
__device__ double g_stats[24];  // [0:4) bn1 sum, [4:8) bn1 sumsq, [8:16) bn2 sum, [16:24) bn2 sumsq
__device__ int    g_sink;

__global__ void k_zero() { if (threadIdx.x < 24) g_stats[threadIdx.x] = 0.0; }
__global__ void k_pad1() { if (threadIdx.x == 0) g_sink = 1; }
__global__ void k_pad2() { if (threadIdx.x == 0) g_sink = 2; }

// ---- f32x2 packed-math helpers ----
__device__ __forceinline__ unsigned long long ffma2(unsigned long long a,
                                                    unsigned long long b,
                                                    unsigned long long c) {
    unsigned long long d;
    asm("fma.rn.f32x2 %0, %1, %2, %3;" : "=l"(d) : "l"(a), "l"(b), "l"(c));
    return d;
}
__device__ __forceinline__ unsigned long long packbc(float x) {  // (x, x)
    unsigned long long d;
    asm("mov.b64 %0, {%1, %2};" : "=l"(d) : "f"(x), "f"(x));
    return d;
}
__device__ __forceinline__ void unpack2(unsigned long long v, float& lo, float& hi) {
    asm("mov.b64 {%0, %1}, %2;" : "=f"(lo), "=f"(hi) : "l"(v));
}

// ---------------- conv1 + bias + relu + maxpool2 + bn1-stats (R5/R3 version) ----------------
__global__ __launch_bounds__(160) void k_conv1(
    const float* __restrict__ x, const float* __restrict__ cw,
    const float* __restrict__ cb)
{
    __shared__ __align__(16) float sm_in[3 * 3460];  // planar [3][27][128], plane stride 3460
    __shared__ __align__(16) float sm_w[972];        // [ic][kh][kw][oc]
    __shared__ float sm_b[4];
    __shared__ float s_part[5][8];
    const int tid = threadIdx.x;
    const int n   = blockIdx.y;
    const int r0  = blockIdx.x * 5;

    if (tid < 4) sm_b[tid] = cb[tid];
    for (int i = tid; i < 972; i += 160) {
        int oc = i & 3; int rest = i >> 2;
        int kw = rest % 9; int t2 = rest / 9; int kh = t2 % 9; int ic = t2 / 9;
        sm_w[i] = cw[oc * 243 + ic * 81 + kh * 9 + kw];
    }
    const float4* xb = (const float4*)(x + (size_t)n * 49152 + (size_t)r0 * 1536);
    for (int i = tid; i < 864; i += 160) {            // 27 rows x 32 groups
        int row = i >> 5; int g = i & 31;
        const float4* src = xb + row * 96 + g * 3;
        float4 a = src[0], b = src[1], c = src[2];
        int base = row * 128 + 4 * g;
        *(float4*)(sm_in + base)            = make_float4(a.x, a.w, b.z, c.y);
        *(float4*)(sm_in + 3460 + base)     = make_float4(a.y, b.x, b.w, c.z);
        *(float4*)(sm_in + 6920 + base)     = make_float4(a.z, b.y, c.x, c.w);
    }
    __syncthreads();

    const bool valid = (tid < 150);
    const int pw  = tid % 30;
    const int phl = valid ? (tid / 30) : 4;

    unsigned long long acc[2][2][2];
    #pragma unroll
    for (int p = 0; p < 2; p++)
        #pragma unroll
        for (int dy = 0; dy < 2; dy++) { acc[p][dy][0] = 0ull; acc[p][dy][1] = 0ull; }

    #pragma unroll 1
    for (int ic = 0; ic < 3; ic++) {
        const float* pl = sm_in + ic * 3460 + phl * 512 + pw * 4;
        const float* wb = sm_w + ic * 324;
        #pragma unroll 1
        for (int kh = 0; kh < 9; kh++) {
            unsigned long long bpa[11], bpb[11];
            {
                const float* rp = pl + kh * 128;
                float4 va = *(const float4*)(rp);
                float4 vb = *(const float4*)(rp + 4);
                float4 vc = *(const float4*)(rp + 8);
                float in[12] = {va.x, va.y, va.z, va.w, vb.x, vb.y, vb.z, vb.w,
                                vc.x, vc.y, vc.z, vc.w};
                #pragma unroll
                for (int j = 0; j < 11; j++) bpa[j] = packbc(in[j]);
            }
            {
                const float* rp = pl + (kh + 2) * 128;
                float4 va = *(const float4*)(rp);
                float4 vb = *(const float4*)(rp + 4);
                float4 vc = *(const float4*)(rp + 8);
                float in[12] = {va.x, va.y, va.z, va.w, vb.x, vb.y, vb.z, vb.w,
                                vc.x, vc.y, vc.z, vc.w};
                #pragma unroll
                for (int j = 0; j < 11; j++) bpb[j] = packbc(in[j]);
            }
            #pragma unroll
            for (int kw = 0; kw < 9; kw++) {
                ulonglong2 w2 = *(const ulonglong2*)(wb + (kh * 9 + kw) * 4);
                acc[0][0][0] = ffma2(w2.x, bpa[kw],     acc[0][0][0]);
                acc[0][0][1] = ffma2(w2.x, bpa[kw + 2], acc[0][0][1]);
                acc[1][0][0] = ffma2(w2.y, bpa[kw],     acc[1][0][0]);
                acc[1][0][1] = ffma2(w2.y, bpa[kw + 2], acc[1][0][1]);
                acc[0][1][0] = ffma2(w2.x, bpb[kw],     acc[0][1][0]);
                acc[0][1][1] = ffma2(w2.x, bpb[kw + 2], acc[0][1][1]);
                acc[1][1][0] = ffma2(w2.y, bpb[kw],     acc[1][1][0]);
                acc[1][1][1] = ffma2(w2.y, bpb[kw + 2], acc[1][1][1]);
            }
        }
    }
    float m4[4];
    #pragma unroll
    for (int p = 0; p < 2; p++) {
        float l00, h00, l01, h01, l10, h10, l11, h11;
        unpack2(acc[p][0][0], l00, h00);
        unpack2(acc[p][0][1], l01, h01);
        unpack2(acc[p][1][0], l10, h10);
        unpack2(acc[p][1][1], l11, h11);
        m4[2 * p]     = fmaxf(fmaxf(l00, l01), fmaxf(l10, l11));
        m4[2 * p + 1] = fmaxf(fmaxf(h00, h01), fmaxf(h10, h11));
    }
    const int ph = r0 + phl;
    float vs[4], vq[4];
    #pragma unroll
    for (int oc = 0; oc < 4; oc++) {
        float m = fmaxf(m4[oc] + sm_b[oc], 0.f);
        if (valid) g_buf1[((n * 4 + oc) * 30 + ph) * 30 + pw] = m;
        vs[oc] = valid ? m : 0.f;
        vq[oc] = valid ? m * m : 0.f;
    }
    #pragma unroll
    for (int oc = 0; oc < 4; oc++)
        #pragma unroll
        for (int off = 16; off > 0; off >>= 1) {
            vs[oc] += __shfl_xor_sync(0xffffffffu, vs[oc], off);
            vq[oc] += __shfl_xor_sync(0xffffffffu, vq[oc], off);
        }
    const int wp = tid >> 5;
    if ((tid & 31) == 0) {
        #pragma unroll
        for (int oc = 0; oc < 4; oc++) {
            s_part[wp][oc]     = vs[oc];
            s_part[wp][4 + oc] = vq[oc];
        }
    }
    __syncthreads();
    if (tid < 8) {
        float t = 0.f;
        #pragma unroll
        for (int w = 0; w < 5; w++) t += s_part[w][tid];
        atomicAdd(&g_stats[tid], (double)t);
    }
}

// ---------------- bn1-apply + conv2 + relu + pool + bn2-stats (R5 version) ----------------
#define C2_IS  3844
#define C2_DSM (8 * C2_IS * 4)

__global__ __launch_bounds__(224) void k_conv2(
    const float* __restrict__ cw, const float* __restrict__ cb,
    const float* __restrict__ g1, const float* __restrict__ b1)
{
    extern __shared__ __align__(16) float c2sm[];
    __shared__ __align__(16) float sm_w[2592];   // [(ic*9+kh)*9+kw]*8 + oc
    __shared__ float sm_b[8];
    __shared__ float sc[4], shh[4];
    __shared__ float s_part[7][16];
    const int tid = threadIdx.x;
    const int n0  = blockIdx.x * 8;

    if (tid < 4) {
        double mu  = g_stats[tid] * (1.0 / 720000.0);
        double var = g_stats[4 + tid] * (1.0 / 720000.0) - mu * mu;
        float scale = g1[tid] * rsqrtf((float)var + 1e-5f);
        sc[tid] = scale; shh[tid] = b1[tid] - (float)mu * scale;
    }
    if (tid < 8) sm_b[tid] = cb[tid];
    for (int i = tid; i < 2592; i += 224) {
        int oc = i & 7; int rest = i >> 3;
        int kw = rest % 9; int t2 = rest / 9; int kh = t2 % 9; int ic = t2 / 9;
        sm_w[i] = cw[oc * 324 + ic * 81 + kh * 9 + kw];
    }
    __syncthreads();   // sc/shh ready for staging

    {
        int img = tid / 25;
        int l25 = tid - img * 25;
        if (img < 8) {
            const float* srcp = g_buf1 + (size_t)(n0 + img) * 3600;
            float* dimg = c2sm + img * C2_IS;
            int ic = 0, row = 0, col = l25;
            for (int i = l25; i < 3600; i += 25) {
                float v = fmaf(srcp[i], sc[ic], shh[ic]);
                int chunk = col >> 2, within = col & 3;
                dimg[ic * 960 + row * 32 + (((chunk ^ (row & 7)) << 2) | within)] = v;
                col += 25;
                if (col >= 30) { col -= 30; row++; if (row >= 30) { row = 0; ic++; } }
            }
        }
    }
    __syncthreads();

    const bool valid = (tid < 200);
    const int img = valid ? (tid / 25) : 7;
    const int l25 = tid % 25;
    const int pr = l25 / 5, pc = l25 - pr * 5;

    unsigned long long acc[4][2][2];
    #pragma unroll
    for (int q = 0; q < 4; q++)
        #pragma unroll
        for (int dy = 0; dy < 2; dy++) { acc[q][dy][0] = 0ull; acc[q][dy][1] = 0ull; }

    const float* ib0 = c2sm + img * C2_IS;
    #pragma unroll 1
    for (int ic = 0; ic < 4; ic++) {
        const float* ib = ib0 + ic * 960;
        const float* wb = sm_w + ic * 648;
        #pragma unroll 1
        for (int kh = 0; kh < 9; kh++) {
            unsigned long long bpa[11], bpb[11];
            {
                int row = 4 * pr + kh;
                int rb = row * 32, rx = row & 7;
                float4 v0 = *(const float4*)(ib + rb + (((pc    ) ^ rx) << 2));
                float4 v1 = *(const float4*)(ib + rb + (((pc + 1) ^ rx) << 2));
                float4 v2 = *(const float4*)(ib + rb + (((pc + 2) ^ rx) << 2));
                float in[12] = {v0.x, v0.y, v0.z, v0.w, v1.x, v1.y, v1.z, v1.w,
                                v2.x, v2.y, v2.z, v2.w};
                #pragma unroll
                for (int j = 0; j < 11; j++) bpa[j] = packbc(in[j]);
            }
            {
                int row = 4 * pr + kh + 2;
                int rb = row * 32, rx = row & 7;
                float4 v0 = *(const float4*)(ib + rb + (((pc    ) ^ rx) << 2));
                float4 v1 = *(const float4*)(ib + rb + (((pc + 1) ^ rx) << 2));
                float4 v2 = *(const float4*)(ib + rb + (((pc + 2) ^ rx) << 2));
                float in[12] = {v0.x, v0.y, v0.z, v0.w, v1.x, v1.y, v1.z, v1.w,
                                v2.x, v2.y, v2.z, v2.w};
                #pragma unroll
                for (int j = 0; j < 11; j++) bpb[j] = packbc(in[j]);
            }
            #pragma unroll
            for (int kw = 0; kw < 9; kw++) {
                ulonglong2 wlo = *(const ulonglong2*)(wb + (kh * 9 + kw) * 8);
                ulonglong2 whi = *(const ulonglong2*)(wb + (kh * 9 + kw) * 8 + 4);
                acc[0][0][0] = ffma2(wlo.x, bpa[kw],     acc[0][0][0]);
                acc[0][0][1] = ffma2(wlo.x, bpa[kw + 2], acc[0][0][1]);
                acc[1][0][0] = ffma2(wlo.y, bpa[kw],     acc[1][0][0]);
                acc[1][0][1] = ffma2(wlo.y, bpa[kw + 2], acc[1][0][1]);
                acc[2][0][0] = ffma2(whi.x, bpa[kw],     acc[2][0][0]);
                acc[2][0][1] = ffma2(whi.x, bpa[kw + 2], acc[2][0][1]);
                acc[3][0][0] = ffma2(whi.y, bpa[kw],     acc[3][0][0]);
                acc[3][0][1] = ffma2(whi.y, bpa[kw + 2], acc[3][0][1]);
                acc[0][1][0] = ffma2(wlo.x, bpb[kw],     acc[0][1][0]);
                acc[0][1][1] = ffma2(wlo.x, bpb[kw + 2], acc[0][1][1]);
                acc[1][1][0] = ffma2(wlo.y, bpb[kw],     acc[1][1][0]);
                acc[1][1][1] = ffma2(wlo.y, bpb[kw + 2], acc[1][1][1]);
                acc[2][1][0] = ffma2(whi.x, bpb[kw],     acc[2][1][0]);
                acc[2][1][1] = ffma2(whi.x, bpb[kw + 2], acc[2][1][1]);
                acc[3][1][0] = ffma2(whi.y, bpb[kw],     acc[3][1][0]);
                acc[3][1][1] = ffma2(whi.y, bpb[kw + 2], acc[3][1][1]);
            }
        }
    }
    float vs[8], vq[8];
    #pragma unroll
    for (int q = 0; q < 4; q++) {
        float l00, h00, l01, h01, l10, h10, l11, h11;
        unpack2(acc[q][0][0], l00, h00);
        unpack2(acc[q][0][1], l01, h01);
        unpack2(acc[q][1][0], l10, h10);
        unpack2(acc[q][1][1], l11, h11);
        float mlo = fmaxf(fmaxf(l00, l01), fmaxf(l10, l11));
        float mhi = fmaxf(fmaxf(h00, h01), fmaxf(h10, h11));
        float a0 = fmaxf(mlo + sm_b[2 * q],     0.f);
        float a1 = fmaxf(mhi + sm_b[2 * q + 1], 0.f);
        if (valid) {
            g_buf2[((n0 + img) * 8 + 2 * q)     * 25 + l25] = a0;
            g_buf2[((n0 + img) * 8 + 2 * q + 1) * 25 + l25] = a1;
        }
        vs[2 * q]     = valid ? a0 : 0.f;
        vs[2 * q + 1] = valid ? a1 : 0.f;
        vq[2 * q]     = valid ? a0 * a0 : 0.f;
        vq[2 * q + 1] = valid ? a1 * a1 : 0.f;
    }
    #pragma unroll
    for (int oc = 0; oc < 8; oc++)
        #pragma unroll
        for (int off = 16; off > 0; off >>= 1) {
            vs[oc] += __shfl_xor_sync(0xffffffffu, vs[oc], off);
            vq[oc] += __shfl_xor_sync(0xffffffffu, vq[oc], off);
        }
    const int wp = tid >> 5;
    if ((tid & 31) == 0) {
        #pragma unroll
        for (int oc = 0; oc < 8; oc++) {
            s_part[wp][oc]     = vs[oc];
            s_part[wp][8 + oc] = vq[oc];
        }
    }
    __syncthreads();
    if (tid < 16) {
        float t = 0.f;
        #pragma unroll
        for (int w = 0; w < 7; w++) t += s_part[w][tid];
        atomicAdd(&g_stats[8 + tid], (double)t);
    }
}

// ---------------- bn2-apply + fc stack (R5 version) ----------------
__global__ __launch_bounds__(256) void k_fc(
    const float* __restrict__ W1, const float* __restrict__ b1,
    const float* __restrict__ W2, const float* __restrict__ b2,
    const float* __restrict__ Wz, const float* __restrict__ bz,
    const float* __restrict__ WL, const float* __restrict__ bL,
    const float* __restrict__ g2, const float* __restrict__ be2)
{
    __shared__ float sW1[3200], sW2[512], sWz[64], sWL[96];
    __shared__ float sb1[16], sb2[32], sbz[2], sbL[3];
    __shared__ float sc[8], shh[8];
    const int tid = threadIdx.x;
    if (tid < 8) {
        double mu  = g_stats[8 + tid] * (1.0 / 20000.0);
        double var = g_stats[16 + tid] * (1.0 / 20000.0) - mu * mu;
        float scale = g2[tid] * rsqrtf((float)var + 1e-5f);
        sc[tid] = scale; shh[tid] = be2[tid] - (float)mu * scale;
    }
    for (int i = tid; i < 3200; i += 256) sW1[i] = W1[i];
    for (int i = tid; i < 512;  i += 256) sW2[i] = W2[i];
    if (tid < 64) sWz[tid] = Wz[tid];
    if (tid < 96) sWL[tid] = WL[tid];
    if (tid < 16) sb1[tid] = b1[tid];
    if (tid < 32) sb2[tid] = b2[tid];
    if (tid < 2)  sbz[tid] = bz[tid];
    if (tid < 3)  sbL[tid] = bL[tid];
    __syncthreads();

    const int lane = tid & 31;
    const int n = blockIdx.x * 8 + (tid >> 5);
    const float* src = g_buf2 + n * 200;

    float p[16];
    #pragma unroll
    for (int i = 0; i < 16; i++) p[i] = 0.f;
    #pragma unroll
    for (int k = 0; k < 7; k++) {
        int j = lane + 32 * k;
        if (j < 200) {
            int ch = j / 25;
            float fv = fmaf(src[j], sc[ch], shh[ch]);
            #pragma unroll
            for (int i = 0; i < 16; i++) p[i] = fmaf(sW1[i * 200 + j], fv, p[i]);
        }
    }
    #pragma unroll
    for (int i = 0; i < 16; i++) {
        #pragma unroll
        for (int off = 16; off > 0; off >>= 1)
            p[i] += __shfl_xor_sync(0xffffffffu, p[i], off);
        p[i] = fmaxf(p[i] + sb1[i], 0.f);
    }
    float a = sb2[lane];
    #pragma unroll
    for (int j = 0; j < 16; j++) a = fmaf(sW2[lane * 16 + j], p[j], a);
    float f2 = fmaxf(a, 0.f);
    float v0 = sWz[lane]      * f2;
    float v1 = sWz[32 + lane] * f2;
    float v2 = sWL[lane]      * f2;
    float v3 = sWL[32 + lane] * f2;
    float v4 = sWL[64 + lane] * f2;
    #pragma unroll
    for (int off = 16; off > 0; off >>= 1) {
        v0 += __shfl_xor_sync(0xffffffffu, v0, off);
        v1 += __shfl_xor_sync(0xffffffffu, v1, off);
        v2 += __shfl_xor_sync(0xffffffffu, v2, off);
        v3 += __shfl_xor_sync(0xffffffffu, v3, off);
        v4 += __shfl_xor_sync(0xffffffffu, v4, off);
    }
    if (lane == 0) {
        g_z[n * 2]     = v0 + sbz[0];
        g_z[n * 2 + 1] = v1 + sbz[1];
        g_L[n * 3]     = v2 + sbL[0];
        g_L[n * 3 + 1] = v3 + sbL[1];
        g_L[n * 3 + 2] = v4 + sbL[2];
    }
}

// ---------------- Kalman filter: 4 lanes per sequence (row-parallel) ----------------
__global__ void k_kf(const float* __restrict__ Ag, const float* __restrict__ Bg,
                     const float* __restrict__ Cg, const float* __restrict__ Qg,
                     float* __restrict__ out)
{
    const int lane = threadIdx.x;
    if (lane >= 32) return;
    const int b   = lane >> 2;
    const int row = lane & 3;

    float A[16], C8[8], Bm[8], Q[4];
    #pragma unroll
    for (int i = 0; i < 16; i++) A[i] = Ag[i];
    #pragma unroll
    for (int i = 0; i < 8; i++)  C8[i] = Cg[i];
    #pragma unroll
    for (int i = 0; i < 8; i++)  Bm[i] = Bg[i];
    #pragma unroll
    for (int i = 0; i < 4; i++)  Q[i] = Qg[i];

    const bool cI = (C8[0] == 1.f && C8[1] == 0.f && C8[2] == 0.f && C8[3] == 0.f &&
                     C8[4] == 0.f && C8[5] == 1.f && C8[6] == 0.f && C8[7] == 0.f);

    if (cI) {
        float BQ[4];
        {
            float bq0 = Bm[row * 2] * Q[0] + Bm[row * 2 + 1] * Q[2];
            float bq1 = Bm[row * 2] * Q[1] + Bm[row * 2 + 1] * Q[3];
            #pragma unroll
            for (int l = 0; l < 4; l++)
                BQ[l] = bq0 * Bm[l * 2] + bq1 * Bm[l * 2 + 1];
        }
        float Ar[4] = {A[row * 4], A[row * 4 + 1], A[row * 4 + 2], A[row * 4 + 3]};
        const float* zp = g_z + b * 200;
        const float* Lp = g_L + b * 300;
        float h = (row == 0) ? zp[0] : (row == 1 ? zp[1] : 0.f);
        float l0 = Lp[0], l1 = Lp[1], l2 = Lp[2];
        float s[4];
        if (row == 0)      { s[0] = l0 * l0; s[1] = l0 * l1;            s[2] = 0.f; s[3] = 0.f; }
        else if (row == 1) { s[0] = l0 * l1; s[1] = l1 * l1 + l2 * l2;  s[2] = 0.f; s[3] = 0.f; }
        else if (row == 2) { s[0] = 0.f; s[1] = 0.f; s[2] = 1.f; s[3] = 0.f; }
        else               { s[0] = 0.f; s[1] = 0.f; s[2] = 0.f; s[3] = 1.f; }
        float* ob = out + b * 400;
        ob[row] = h;

        float nzx = zp[2], nzy = zp[3];
        float nLa = Lp[3], nLb = Lp[4], nLc = Lp[5];

        for (int t = 1; t < 100; t++) {
            float zx = nzx, zy = nzy;
            float La = nLa, Lb = nLb, Lc = nLc;
            if (t < 99) {
                nzx = zp[(t + 1) * 2];  nzy = zp[(t + 1) * 2 + 1];
                nLa = Lp[(t + 1) * 3];  nLb = Lp[(t + 1) * 3 + 1];
                nLc = Lp[(t + 1) * 3 + 2];
            }
            float r00 = La * La, r01 = La * Lb, r11 = Lb * Lb + Lc * Lc;

            float hp = 0.f;
            #pragma unroll
            for (int k = 0; k < 4; k++)
                hp = fmaf(Ar[k], __shfl_sync(0xffffffffu, h, k, 4), hp);

            float tmp[4] = {0.f, 0.f, 0.f, 0.f};
            #pragma unroll
            for (int k = 0; k < 4; k++) {
                #pragma unroll
                for (int j = 0; j < 4; j++)
                    tmp[j] = fmaf(Ar[k], __shfl_sync(0xffffffffu, s[j], k, 4), tmp[j]);
            }
            float sp[4];
            #pragma unroll
            for (int l = 0; l < 4; l++)
                sp[l] = BQ[l] + tmp[0] * A[l * 4] + tmp[1] * A[l * 4 + 1]
                              + tmp[2] * A[l * 4 + 2] + tmp[3] * A[l * 4 + 3];

            float sr0[4], sr1[4];
            #pragma unroll
            for (int l = 0; l < 4; l++) {
                sr0[l] = __shfl_sync(0xffffffffu, sp[l], 0, 4);
                sr1[l] = __shfl_sync(0xffffffffu, sp[l], 1, 4);
            }
            float S00 = sr0[0] + r00, S01 = sr0[1] + r01;
            float S10 = sr1[0] + r01, S11 = sr1[1] + r11;
            float idet = 1.f / (S00 * S11 - S01 * S10);
            float Si00 = S11 * idet, Si01 = -S01 * idet;
            float Si10 = -S10 * idet, Si11 = S00 * idet;
            float K0 = sp[0] * Si00 + sp[1] * Si10;
            float K1 = sp[0] * Si01 + sp[1] * Si11;

            float hp0 = __shfl_sync(0xffffffffu, hp, 0, 4);
            float hp1 = __shfl_sync(0xffffffffu, hp, 1, 4);
            float a0 = zx - hp0, a1 = zy - hp1;
            h = hp + K0 * a0 + K1 * a1;

            #pragma unroll
            for (int l = 0; l < 4; l++)
                s[l] = sp[l] - K0 * sr0[l] - K1 * sr1[l];

            ob[t * 4 + row] = h;
        }
        return;
    }

    // ---- general-C fallback: serial per sequence (8 active lanes) ----
    if (row != 0) return;
    float BQBT[16];
    #pragma unroll
    for (int i = 0; i < 4; i++) {
        float bq0 = Bm[i * 2] * Q[0] + Bm[i * 2 + 1] * Q[2];
        float bq1 = Bm[i * 2] * Q[1] + Bm[i * 2 + 1] * Q[3];
        #pragma unroll
        for (int l = 0; l < 4; l++)
            BQBT[i * 4 + l] = bq0 * Bm[l * 2] + bq1 * Bm[l * 2 + 1];
    }
    const float* zp = g_z + b * 200;
    const float* Lp = g_L + b * 300;
    float h[4] = {zp[0], zp[1], 0.f, 0.f};
    float l0 = Lp[0], l1 = Lp[1], l2 = Lp[2];
    float s[16] = {l0 * l0, l0 * l1, 0.f, 0.f,
                   l0 * l1, l1 * l1 + l2 * l2, 0.f, 0.f,
                   0.f, 0.f, 1.f, 0.f,
                   0.f, 0.f, 0.f, 1.f};
    float* ob = out + b * 400;
    *(float4*)ob = make_float4(h[0], h[1], h[2], h[3]);

    for (int t = 1; t < 100; t++) {
        float zx = zp[t * 2], zy = zp[t * 2 + 1];
        float La = Lp[t * 3], Lb = Lp[t * 3 + 1], Lc = Lp[t * 3 + 2];
        float r00 = La * La, r01 = La * Lb, r11 = Lb * Lb + Lc * Lc;
        float hp[4];
        #pragma unroll
        for (int i = 0; i < 4; i++)
            hp[i] = A[i*4]*h[0] + A[i*4+1]*h[1] + A[i*4+2]*h[2] + A[i*4+3]*h[3];
        float tmp[16];
        #pragma unroll
        for (int i = 0; i < 4; i++)
            #pragma unroll
            for (int k = 0; k < 4; k++)
                tmp[i*4+k] = A[i*4]*s[k] + A[i*4+1]*s[4+k] + A[i*4+2]*s[8+k] + A[i*4+3]*s[12+k];
        float sp[16];
        #pragma unroll
        for (int i = 0; i < 4; i++)
            #pragma unroll
            for (int l = 0; l < 4; l++)
                sp[i*4+l] = BQBT[i*4+l] + tmp[i*4]*A[l*4] + tmp[i*4+1]*A[l*4+1]
                          + tmp[i*4+2]*A[l*4+2] + tmp[i*4+3]*A[l*4+3];
        float sct[8];
        #pragma unroll
        for (int i = 0; i < 4; i++)
            #pragma unroll
            for (int j = 0; j < 2; j++)
                sct[i*2+j] = sp[i*4]*C8[j*4] + sp[i*4+1]*C8[j*4+1]
                           + sp[i*4+2]*C8[j*4+2] + sp[i*4+3]*C8[j*4+3];
        float S00 = C8[0]*sct[0] + C8[1]*sct[2] + C8[2]*sct[4] + C8[3]*sct[6] + r00;
        float S01 = C8[0]*sct[1] + C8[1]*sct[3] + C8[2]*sct[5] + C8[3]*sct[7] + r01;
        float S10 = C8[4]*sct[0] + C8[5]*sct[2] + C8[6]*sct[4] + C8[7]*sct[6] + r01;
        float S11 = C8[4]*sct[1] + C8[5]*sct[3] + C8[6]*sct[5] + C8[7]*sct[7] + r11;
        float idet = 1.f / (S00 * S11 - S01 * S10);
        float Si00 = S11 * idet, Si01 = -S01 * idet, Si10 = -S10 * idet, Si11 = S00 * idet;
        float K[8];
        #pragma unroll
        for (int i = 0; i < 4; i++) {
            K[i*2]   = sct[i*2]*Si00 + sct[i*2+1]*Si10;
            K[i*2+1] = sct[i*2]*Si01 + sct[i*2+1]*Si11;
        }
        float a0 = zx - (C8[0]*hp[0] + C8[1]*hp[1] + C8[2]*hp[2] + C8[3]*hp[3]);
        float a1 = zy - (C8[4]*hp[0] + C8[5]*hp[1] + C8[6]*hp[2] + C8[7]*hp[3]);
        #pragma unroll
        for (int i = 0; i < 4; i++) h[i] = hp[i] + K[i*2]*a0 + K[i*2+1]*a1;
        float M[16];
        #pragma unroll
        for (int i = 0; i < 4; i++)
            #pragma unroll
            for (int j = 0; j < 4; j++)
                M[i*4+j] = (i == j ? 1.f : 0.f) - (K[i*2]*C8[j] + K[i*2+1]*C8[4+j]);
        #pragma unroll
        for (int i = 0; i < 4; i++)
            #pragma unroll
            for (int l = 0; l < 4; l++)
                s[i*4+l] = M[i*4]*sp[l] + M[i*4+1]*sp[4+l]
                         + M[i*4+2]*sp[8+l] + M[i*4+3]*sp[12+l];
        *(float4*)(ob + t * 4) = make_float4(h[0], h[1], h[2], h[3]);
    }
}

extern "C" void kernel_launch(void* const* d_in, const int* in_sizes, int n_in,
                              void* d_out, int out_size) {
    const float* x    = (const float*)d_in[0];
    const float* c1w  = (const float*)d_in[1];
    const float* c1b  = (const float*)d_in[2];
    const float* bn1g = (const float*)d_in[3];
    const float* bn1b = (const float*)d_in[4];
    const float* c2w  = (const float*)d_in[5];
    const float* c2b  = (const float*)d_in[6];
    const float* bn2g = (const float*)d_in[7];
    const float* bn2b = (const float*)d_in[8];
    const float* W1   = (const float*)d_in[9];
    const float* b1   = (const float*)d_in[10];
    const float* W2   = (const float*)d_in[11];
    const float* b2   = (const float*)d_in[12];
    const float* Wz   = (const float*)d_in[13];
    const float* bz   = (const float*)d_in[14];
    const float* WL   = (const float*)d_in[15];
    const float* bL   = (const float*)d_in[16];
    const float* A    = (const float*)d_in[17];
    const float* B    = (const float*)d_in[18];
    const float* C    = (const float*)d_in[19];
    const float* Q    = (const float*)d_in[20];
    float* out = (float*)d_out;

    static int attr_done = 0;
    if (!attr_done) {
        cudaFuncSetAttribute(k_conv2, cudaFuncAttributeMaxDynamicSharedMemorySize, C2_DSM);
        attr_done = 1;
    }

    k_zero<<<1, 32>>>();
    k_pad1<<<1, 32>>>();
    k_pad2<<<1, 32>>>();
    k_conv1<<<dim3(6, 800), 160>>>(x, c1w, c1b);
    k_conv2<<<100, 224, C2_DSM>>>(c2w, c2b, bn1g, bn1b);
    k_fc<<<100, 256>>>(W1, b1, W2, b2, Wz, bz, WL, bL, bn2g, bn2b);
    k_kf<<<1, 32>>>(A, B, C, Q, out);
}

// round 11
// speedup vs baseline: 1.0590x; 1.0004x over previous
#include <cuda_runtime.h>

#define NIMG 800

// ---------------- scratch (no allocation allowed) ----------------
__device__ float  g_buf1[NIMG * 4 * 30 * 30];   // conv1 pooled output (NCHW)
__device__ float  g_buf2[NIMG * 8 * 25];        // conv2 pooled output (NCHW)
__device__ float  g_z[NIMG * 2];
__device__ float  g_L[NIMG * 3];
__device__ double g_stats[24];  // [0:4) bn1 sum, [4:8) bn1 sumsq, [8:16) bn2 sum, [16:24) bn2 sumsq
__device__ int    g_sink;

__global__ void k_zero() { if (threadIdx.x < 24) g_stats[threadIdx.x] = 0.0; }
__global__ void k_pad1() { if (threadIdx.x == 0) g_sink = 1; }
__global__ void k_pad2() { if (threadIdx.x == 0) g_sink = 2; }

// ---- f32x2 packed-math helpers ----
__device__ __forceinline__ unsigned long long ffma2(unsigned long long a,
                                                    unsigned long long b,
                                                    unsigned long long c) {
    unsigned long long d;
    asm("fma.rn.f32x2 %0, %1, %2, %3;" : "=l"(d) : "l"(a), "l"(b), "l"(c));
    return d;
}
__device__ __forceinline__ unsigned long long packbc(float x) {  // (x, x)
    unsigned long long d;
    asm("mov.b64 %0, {%1, %2};" : "=l"(d) : "f"(x), "f"(x));
    return d;
}
__device__ __forceinline__ void unpack2(unsigned long long v, float& lo, float& hi) {
    asm("mov.b64 {%0, %1}, %2;" : "=f"(lo), "=f"(hi) : "l"(v));
}

// load one input row (12 floats via 3x LDS.128) and broadcast-pack 11 windows
__device__ __forceinline__ void c1_load_row(const float* rp, unsigned long long bp[11]) {
    float4 va = *(const float4*)(rp);
    float4 vb = *(const float4*)(rp + 4);
    float4 vc = *(const float4*)(rp + 8);
    float in[12] = {va.x, va.y, va.z, va.w, vb.x, vb.y, vb.z, vb.w,
                    vc.x, vc.y, vc.z, vc.w};
    #pragma unroll
    for (int j = 0; j < 11; j++) bp[j] = packbc(in[j]);
}

// one kh step: weights w[kh] applied to 4 consumer rows.
// Ra=(o0,dy0) row kh, Rb=(o0,dy1) row kh+2, Rc=(o1,dy0) row kh+4, Rd=(o1,dy1) row kh+6.
__device__ __forceinline__ void c1_step(const float* wb, int kh,
                                        const unsigned long long Ra[11],
                                        const unsigned long long Rb[11],
                                        const unsigned long long Rc[11],
                                        const unsigned long long Rd[11],
                                        unsigned long long acc[2][2][2][2]) {
    #pragma unroll
    for (int kw = 0; kw < 9; kw++) {
        ulonglong2 w2 = *(const ulonglong2*)(wb + (kh * 9 + kw) * 4);
        acc[0][0][0][0] = ffma2(w2.x, Ra[kw],     acc[0][0][0][0]);
        acc[0][0][0][1] = ffma2(w2.x, Ra[kw + 2], acc[0][0][0][1]);
        acc[1][0][0][0] = ffma2(w2.y, Ra[kw],     acc[1][0][0][0]);
        acc[1][0][0][1] = ffma2(w2.y, Ra[kw + 2], acc[1][0][0][1]);
        acc[0][0][1][0] = ffma2(w2.x, Rb[kw],     acc[0][0][1][0]);
        acc[0][0][1][1] = ffma2(w2.x, Rb[kw + 2], acc[0][0][1][1]);
        acc[1][0][1][0] = ffma2(w2.y, Rb[kw],     acc[1][0][1][0]);
        acc[1][0][1][1] = ffma2(w2.y, Rb[kw + 2], acc[1][0][1][1]);
        acc[0][1][0][0] = ffma2(w2.x, Rc[kw],     acc[0][1][0][0]);
        acc[0][1][0][1] = ffma2(w2.x, Rc[kw + 2], acc[0][1][0][1]);
        acc[1][1][0][0] = ffma2(w2.y, Rc[kw],     acc[1][1][0][0]);
        acc[1][1][0][1] = ffma2(w2.y, Rc[kw + 2], acc[1][1][0][1]);
        acc[0][1][1][0] = ffma2(w2.x, Rd[kw],     acc[0][1][1][0]);
        acc[0][1][1][1] = ffma2(w2.x, Rd[kw + 2], acc[0][1][1][1]);
        acc[1][1][1][0] = ffma2(w2.y, Rd[kw],     acc[1][1][1][0]);
        acc[1][1][1][1] = ffma2(w2.y, Rd[kw + 2], acc[1][1][1][1]);
    }
}

// ---------------- conv1 + bias + relu + maxpool2 + bn1-stats ----------------
// Vertical pooled PAIR per thread: block = 8 pooled rows x 30 cols (120 workers).
// 4-row rolling packed buffers; every input row loaded+packed once; weights once per (kh,kw).
#define C1_ROWS  39
#define C1_PLANE (C1_ROWS * 128)     // 4992 floats/plane
#define C1_DSM   (3 * C1_PLANE * 4)  // 59904 bytes

__global__ __launch_bounds__(128, 3) void k_conv1(
    const float* __restrict__ x, const float* __restrict__ cw,
    const float* __restrict__ cb)
{
    extern __shared__ __align__(16) float dsm[];
    __shared__ __align__(16) float sm_w[972];   // [ic][kh][kw][oc]
    __shared__ float sm_b[4];
    __shared__ float s_part[4][8];
    const int tid = threadIdx.x;
    const int n   = blockIdx.y;
    const int bx  = blockIdx.x;                  // 0..3, pooled rows 8*bx ..

    if (tid < 4) sm_b[tid] = cb[tid];
    for (int i = tid; i < 972; i += 128) {
        int oc = i & 3; int rest = i >> 2;
        int kw = rest % 9; int t2 = rest / 9; int kh = t2 % 9; int ic = t2 / 9;
        sm_w[i] = cw[oc * 243 + ic * 81 + kh * 9 + kw];
    }
    // stage up to 39 input rows starting at image row 32*bx
    const int nrows = min(C1_ROWS, 128 - 32 * bx);
    const float4* xb = (const float4*)(x + (size_t)n * 49152 + (size_t)(32 * bx) * 384);
    for (int i = tid; i < nrows * 32; i += 128) {
        int row = i >> 5; int g = i & 31;
        const float4* src = xb + row * 96 + g * 3;
        float4 a = src[0], b = src[1], c = src[2];
        int base = row * 128 + 4 * g;
        *(float4*)(dsm + base)                = make_float4(a.x, a.w, b.z, c.y);
        *(float4*)(dsm + C1_PLANE + base)     = make_float4(a.y, b.x, b.w, c.z);
        *(float4*)(dsm + 2 * C1_PLANE + base) = make_float4(a.z, b.y, c.x, c.w);
    }
    __syncthreads();

    const int pr = (tid < 120) ? (tid / 30) : 3;
    const int pw = tid % 30;
    const bool valid = (tid < 120) && (8 * bx + 2 * pr <= 28);

    // acc[ocpair p][o][dy][dx]
    unsigned long long acc[2][2][2][2];
    #pragma unroll
    for (int p = 0; p < 2; p++)
        #pragma unroll
        for (int o = 0; o < 2; o++)
            #pragma unroll
            for (int dy = 0; dy < 2; dy++) { acc[p][o][dy][0] = 0ull; acc[p][o][dy][1] = 0ull; }

    #pragma unroll 1
    for (int ic = 0; ic < 3; ic++) {
        const float* pl = dsm + ic * C1_PLANE + (8 * pr) * 128 + pw * 4;
        const float* wb = sm_w + ic * 324;
        unsigned long long B0[11], B1[11], B2[11], B3[11];
        // even chain: kh = 0,2,4,6,8; rows kh+{0,2,4,6}
        c1_load_row(pl,            B0);
        c1_load_row(pl + 2 * 128,  B1);
        c1_load_row(pl + 4 * 128,  B2);
        c1_load_row(pl + 6 * 128,  B3);
        c1_step(wb, 0, B0, B1, B2, B3, acc);
        c1_load_row(pl + 8 * 128,  B0);
        c1_step(wb, 2, B1, B2, B3, B0, acc);
        c1_load_row(pl + 10 * 128, B1);
        c1_step(wb, 4, B2, B3, B0, B1, acc);
        c1_load_row(pl + 12 * 128, B2);
        c1_step(wb, 6, B3, B0, B1, B2, acc);
        c1_load_row(pl + 14 * 128, B3);
        c1_step(wb, 8, B0, B1, B2, B3, acc);
        // odd chain: kh = 1,3,5,7; rows kh+{0,2,4,6}
        c1_load_row(pl + 1 * 128,  B0);
        c1_load_row(pl + 3 * 128,  B1);
        c1_load_row(pl + 5 * 128,  B2);
        c1_load_row(pl + 7 * 128,  B3);
        c1_step(wb, 1, B0, B1, B2, B3, acc);
        c1_load_row(pl + 9 * 128,  B0);
        c1_step(wb, 3, B1, B2, B3, B0, acc);
        c1_load_row(pl + 11 * 128, B1);
        c1_step(wb, 5, B2, B3, B0, B1, acc);
        c1_load_row(pl + 13 * 128, B2);
        c1_step(wb, 7, B3, B0, B1, B2, acc);
    }
    // unpack, pool, bias, relu, store two pooled rows per oc
    const int ph0 = 8 * bx + 2 * pr;
    float vs[4], vq[4];
    #pragma unroll
    for (int p = 0; p < 2; p++) {
        float a0v[2], a1v[2];   // [lo/hi oc of pair] for o=0 and o=1
        #pragma unroll
        for (int o = 0; o < 2; o++) {
            float l00, h00, l01, h01, l10, h10, l11, h11;
            unpack2(acc[p][o][0][0], l00, h00);
            unpack2(acc[p][o][0][1], l01, h01);
            unpack2(acc[p][o][1][0], l10, h10);
            unpack2(acc[p][o][1][1], l11, h11);
            float mlo = fmaxf(fmaxf(l00, l01), fmaxf(l10, l11));
            float mhi = fmaxf(fmaxf(h00, h01), fmaxf(h10, h11));
            if (o == 0) { a0v[0] = mlo; a0v[1] = mhi; }
            else        { a1v[0] = mlo; a1v[1] = mhi; }
        }
        #pragma unroll
        for (int half = 0; half < 2; half++) {
            int oc = 2 * p + half;
            float b = sm_b[oc];
            float r0 = fmaxf(a0v[half] + b, 0.f);
            float r1 = fmaxf(a1v[half] + b, 0.f);
            if (valid) {
                g_buf1[((n * 4 + oc) * 30 + ph0)     * 30 + pw] = r0;
                g_buf1[((n * 4 + oc) * 30 + ph0 + 1) * 30 + pw] = r1;
            }
            vs[oc] = valid ? (r0 + r1) : 0.f;
            vq[oc] = valid ? (r0 * r0 + r1 * r1) : 0.f;
        }
    }
    #pragma unroll
    for (int oc = 0; oc < 4; oc++)
        #pragma unroll
        for (int off = 16; off > 0; off >>= 1) {
            vs[oc] += __shfl_xor_sync(0xffffffffu, vs[oc], off);
            vq[oc] += __shfl_xor_sync(0xffffffffu, vq[oc], off);
        }
    const int wp = tid >> 5;
    if ((tid & 31) == 0) {
        #pragma unroll
        for (int oc = 0; oc < 4; oc++) {
            s_part[wp][oc]     = vs[oc];
            s_part[wp][4 + oc] = vq[oc];
        }
    }
    __syncthreads();
    if (tid < 8) {
        float t = 0.f;
        #pragma unroll
        for (int w = 0; w < 4; w++) t += s_part[w][tid];
        atomicAdd(&g_stats[tid], (double)t);
    }
}

// ---------------- bn1-apply + conv2 + relu + pool + bn2-stats (R5 version) ----------------
#define C2_IS  3844
#define C2_DSM (8 * C2_IS * 4)

__global__ __launch_bounds__(224) void k_conv2(
    const float* __restrict__ cw, const float* __restrict__ cb,
    const float* __restrict__ g1, const float* __restrict__ b1)
{
    extern __shared__ __align__(16) float c2sm[];
    __shared__ __align__(16) float sm_w[2592];
    __shared__ float sm_b[8];
    __shared__ float sc[4], shh[4];
    __shared__ float s_part[7][16];
    const int tid = threadIdx.x;
    const int n0  = blockIdx.x * 8;

    if (tid < 4) {
        double mu  = g_stats[tid] * (1.0 / 720000.0);
        double var = g_stats[4 + tid] * (1.0 / 720000.0) - mu * mu;
        float scale = g1[tid] * rsqrtf((float)var + 1e-5f);
        sc[tid] = scale; shh[tid] = b1[tid] - (float)mu * scale;
    }
    if (tid < 8) sm_b[tid] = cb[tid];
    for (int i = tid; i < 2592; i += 224) {
        int oc = i & 7; int rest = i >> 3;
        int kw = rest % 9; int t2 = rest / 9; int kh = t2 % 9; int ic = t2 / 9;
        sm_w[i] = cw[oc * 324 + ic * 81 + kh * 9 + kw];
    }
    __syncthreads();

    {
        int img = tid / 25;
        int l25 = tid - img * 25;
        if (img < 8) {
            const float* srcp = g_buf1 + (size_t)(n0 + img) * 3600;
            float* dimg = c2sm + img * C2_IS;
            int ic = 0, row = 0, col = l25;
            for (int i = l25; i < 3600; i += 25) {
                float v = fmaf(srcp[i], sc[ic], shh[ic]);
                int chunk = col >> 2, within = col & 3;
                dimg[ic * 960 + row * 32 + (((chunk ^ (row & 7)) << 2) | within)] = v;
                col += 25;
                if (col >= 30) { col -= 30; row++; if (row >= 30) { row = 0; ic++; } }
            }
        }
    }
    __syncthreads();

    const bool valid = (tid < 200);
    const int img = valid ? (tid / 25) : 7;
    const int l25 = tid % 25;
    const int pr = l25 / 5, pc = l25 - pr * 5;

    unsigned long long acc[4][2][2];
    #pragma unroll
    for (int q = 0; q < 4; q++)
        #pragma unroll
        for (int dy = 0; dy < 2; dy++) { acc[q][dy][0] = 0ull; acc[q][dy][1] = 0ull; }

    const float* ib0 = c2sm + img * C2_IS;
    #pragma unroll 1
    for (int ic = 0; ic < 4; ic++) {
        const float* ib = ib0 + ic * 960;
        const float* wb = sm_w + ic * 648;
        #pragma unroll 1
        for (int kh = 0; kh < 9; kh++) {
            unsigned long long bpa[11], bpb[11];
            {
                int row = 4 * pr + kh;
                int rb = row * 32, rx = row & 7;
                float4 v0 = *(const float4*)(ib + rb + (((pc    ) ^ rx) << 2));
                float4 v1 = *(const float4*)(ib + rb + (((pc + 1) ^ rx) << 2));
                float4 v2 = *(const float4*)(ib + rb + (((pc + 2) ^ rx) << 2));
                float in[12] = {v0.x, v0.y, v0.z, v0.w, v1.x, v1.y, v1.z, v1.w,
                                v2.x, v2.y, v2.z, v2.w};
                #pragma unroll
                for (int j = 0; j < 11; j++) bpa[j] = packbc(in[j]);
            }
            {
                int row = 4 * pr + kh + 2;
                int rb = row * 32, rx = row & 7;
                float4 v0 = *(const float4*)(ib + rb + (((pc    ) ^ rx) << 2));
                float4 v1 = *(const float4*)(ib + rb + (((pc + 1) ^ rx) << 2));
                float4 v2 = *(const float4*)(ib + rb + (((pc + 2) ^ rx) << 2));
                float in[12] = {v0.x, v0.y, v0.z, v0.w, v1.x, v1.y, v1.z, v1.w,
                                v2.x, v2.y, v2.z, v2.w};
                #pragma unroll
                for (int j = 0; j < 11; j++) bpb[j] = packbc(in[j]);
            }
            #pragma unroll
            for (int kw = 0; kw < 9; kw++) {
                ulonglong2 wlo = *(const ulonglong2*)(wb + (kh * 9 + kw) * 8);
                ulonglong2 whi = *(const ulonglong2*)(wb + (kh * 9 + kw) * 8 + 4);
                acc[0][0][0] = ffma2(wlo.x, bpa[kw],     acc[0][0][0]);
                acc[0][0][1] = ffma2(wlo.x, bpa[kw + 2], acc[0][0][1]);
                acc[1][0][0] = ffma2(wlo.y, bpa[kw],     acc[1][0][0]);
                acc[1][0][1] = ffma2(wlo.y, bpa[kw + 2], acc[1][0][1]);
                acc[2][0][0] = ffma2(whi.x, bpa[kw],     acc[2][0][0]);
                acc[2][0][1] = ffma2(whi.x, bpa[kw + 2], acc[2][0][1]);
                acc[3][0][0] = ffma2(whi.y, bpa[kw],     acc[3][0][0]);
                acc[3][0][1] = ffma2(whi.y, bpa[kw + 2], acc[3][0][1]);
                acc[0][1][0] = ffma2(wlo.x, bpb[kw],     acc[0][1][0]);
                acc[0][1][1] = ffma2(wlo.x, bpb[kw + 2], acc[0][1][1]);
                acc[1][1][0] = ffma2(wlo.y, bpb[kw],     acc[1][1][0]);
                acc[1][1][1] = ffma2(wlo.y, bpb[kw + 2], acc[1][1][1]);
                acc[2][1][0] = ffma2(whi.x, bpb[kw],     acc[2][1][0]);
                acc[2][1][1] = ffma2(whi.x, bpb[kw + 2], acc[2][1][1]);
                acc[3][1][0] = ffma2(whi.y, bpb[kw],     acc[3][1][0]);
                acc[3][1][1] = ffma2(whi.y, bpb[kw + 2], acc[3][1][1]);
            }
        }
    }
    float vs[8], vq[8];
    #pragma unroll
    for (int q = 0; q < 4; q++) {
        float l00, h00, l01, h01, l10, h10, l11, h11;
        unpack2(acc[q][0][0], l00, h00);
        unpack2(acc[q][0][1], l01, h01);
        unpack2(acc[q][1][0], l10, h10);
        unpack2(acc[q][1][1], l11, h11);
        float mlo = fmaxf(fmaxf(l00, l01), fmaxf(l10, l11));
        float mhi = fmaxf(fmaxf(h00, h01), fmaxf(h10, h11));
        float a0 = fmaxf(mlo + sm_b[2 * q],     0.f);
        float a1 = fmaxf(mhi + sm_b[2 * q + 1], 0.f);
        if (valid) {
            g_buf2[((n0 + img) * 8 + 2 * q)     * 25 + l25] = a0;
            g_buf2[((n0 + img) * 8 + 2 * q + 1) * 25 + l25] = a1;
        }
        vs[2 * q]     = valid ? a0 : 0.f;
        vs[2 * q + 1] = valid ? a1 : 0.f;
        vq[2 * q]     = valid ? a0 * a0 : 0.f;
        vq[2 * q + 1] = valid ? a1 * a1 : 0.f;
    }
    #pragma unroll
    for (int oc = 0; oc < 8; oc++)
        #pragma unroll
        for (int off = 16; off > 0; off >>= 1) {
            vs[oc] += __shfl_xor_sync(0xffffffffu, vs[oc], off);
            vq[oc] += __shfl_xor_sync(0xffffffffu, vq[oc], off);
        }
    const int wp = tid >> 5;
    if ((tid & 31) == 0) {
        #pragma unroll
        for (int oc = 0; oc < 8; oc++) {
            s_part[wp][oc]     = vs[oc];
            s_part[wp][8 + oc] = vq[oc];
        }
    }
    __syncthreads();
    if (tid < 16) {
        float t = 0.f;
        #pragma unroll
        for (int w = 0; w < 7; w++) t += s_part[w][tid];
        atomicAdd(&g_stats[8 + tid], (double)t);
    }
}

// ---------------- bn2-apply + fc stack (R5 version) ----------------
__global__ __launch_bounds__(256) void k_fc(
    const float* __restrict__ W1, const float* __restrict__ b1,
    const float* __restrict__ W2, const float* __restrict__ b2,
    const float* __restrict__ Wz, const float* __restrict__ bz,
    const float* __restrict__ WL, const float* __restrict__ bL,
    const float* __restrict__ g2, const float* __restrict__ be2)
{
    __shared__ float sW1[3200], sW2[512], sWz[64], sWL[96];
    __shared__ float sb1[16], sb2[32], sbz[2], sbL[3];
    __shared__ float sc[8], shh[8];
    const int tid = threadIdx.x;
    if (tid < 8) {
        double mu  = g_stats[8 + tid] * (1.0 / 20000.0);
        double var = g_stats[16 + tid] * (1.0 / 20000.0) - mu * mu;
        float scale = g2[tid] * rsqrtf((float)var + 1e-5f);
        sc[tid] = scale; shh[tid] = be2[tid] - (float)mu * scale;
    }
    for (int i = tid; i < 3200; i += 256) sW1[i] = W1[i];
    for (int i = tid; i < 512;  i += 256) sW2[i] = W2[i];
    if (tid < 64) sWz[tid] = Wz[tid];
    if (tid < 96) sWL[tid] = WL[tid];
    if (tid < 16) sb1[tid] = b1[tid];
    if (tid < 32) sb2[tid] = b2[tid];
    if (tid < 2)  sbz[tid] = bz[tid];
    if (tid < 3)  sbL[tid] = bL[tid];
    __syncthreads();

    const int lane = tid & 31;
    const int n = blockIdx.x * 8 + (tid >> 5);
    const float* src = g_buf2 + n * 200;

    float p[16];
    #pragma unroll
    for (int i = 0; i < 16; i++) p[i] = 0.f;
    #pragma unroll
    for (int k = 0; k < 7; k++) {
        int j = lane + 32 * k;
        if (j < 200) {
            int ch = j / 25;
            float fv = fmaf(src[j], sc[ch], shh[ch]);
            #pragma unroll
            for (int i = 0; i < 16; i++) p[i] = fmaf(sW1[i * 200 + j], fv, p[i]);
        }
    }
    #pragma unroll
    for (int i = 0; i < 16; i++) {
        #pragma unroll
        for (int off = 16; off > 0; off >>= 1)
            p[i] += __shfl_xor_sync(0xffffffffu, p[i], off);
        p[i] = fmaxf(p[i] + sb1[i], 0.f);
    }
    float a = sb2[lane];
    #pragma unroll
    for (int j = 0; j < 16; j++) a = fmaf(sW2[lane * 16 + j], p[j], a);
    float f2 = fmaxf(a, 0.f);
    float v0 = sWz[lane]      * f2;
    float v1 = sWz[32 + lane] * f2;
    float v2 = sWL[lane]      * f2;
    float v3 = sWL[32 + lane] * f2;
    float v4 = sWL[64 + lane] * f2;
    #pragma unroll
    for (int off = 16; off > 0; off >>= 1) {
        v0 += __shfl_xor_sync(0xffffffffu, v0, off);
        v1 += __shfl_xor_sync(0xffffffffu, v1, off);
        v2 += __shfl_xor_sync(0xffffffffu, v2, off);
        v3 += __shfl_xor_sync(0xffffffffu, v3, off);
        v4 += __shfl_xor_sync(0xffffffffu, v4, off);
    }
    if (lane == 0) {
        g_z[n * 2]     = v0 + sbz[0];
        g_z[n * 2 + 1] = v1 + sbz[1];
        g_L[n * 3]     = v2 + sbL[0];
        g_L[n * 3 + 1] = v3 + sbL[1];
        g_L[n * 3 + 2] = v4 + sbL[2];
    }
}

// ---------------- Kalman filter: 4 lanes per sequence (row-parallel) ----------------
__global__ void k_kf(const float* __restrict__ Ag, const float* __restrict__ Bg,
                     const float* __restrict__ Cg, const float* __restrict__ Qg,
                     float* __restrict__ out)
{
    const int lane = threadIdx.x;
    if (lane >= 32) return;
    const int b   = lane >> 2;
    const int row = lane & 3;

    float A[16], C8[8], Bm[8], Q[4];
    #pragma unroll
    for (int i = 0; i < 16; i++) A[i] = Ag[i];
    #pragma unroll
    for (int i = 0; i < 8; i++)  C8[i] = Cg[i];
    #pragma unroll
    for (int i = 0; i < 8; i++)  Bm[i] = Bg[i];
    #pragma unroll
    for (int i = 0; i < 4; i++)  Q[i] = Qg[i];

    const bool cI = (C8[0] == 1.f && C8[1] == 0.f && C8[2] == 0.f && C8[3] == 0.f &&
                     C8[4] == 0.f && C8[5] == 1.f && C8[6] == 0.f && C8[7] == 0.f);

    if (cI) {
        float BQ[4];
        {
            float bq0 = Bm[row * 2] * Q[0] + Bm[row * 2 + 1] * Q[2];
            float bq1 = Bm[row * 2] * Q[1] + Bm[row * 2 + 1] * Q[3];
            #pragma unroll
            for (int l = 0; l < 4; l++)
                BQ[l] = bq0 * Bm[l * 2] + bq1 * Bm[l * 2 + 1];
        }
        float Ar[4] = {A[row * 4], A[row * 4 + 1], A[row * 4 + 2], A[row * 4 + 3]};
        const float* zp = g_z + b * 200;
        const float* Lp = g_L + b * 300;
        float h = (row == 0) ? zp[0] : (row == 1 ? zp[1] : 0.f);
        float l0 = Lp[0], l1 = Lp[1], l2 = Lp[2];
        float s[4];
        if (row == 0)      { s[0] = l0 * l0; s[1] = l0 * l1;            s[2] = 0.f; s[3] = 0.f; }
        else if (row == 1) { s[0] = l0 * l1; s[1] = l1 * l1 + l2 * l2;  s[2] = 0.f; s[3] = 0.f; }
        else if (row == 2) { s[0] = 0.f; s[1] = 0.f; s[2] = 1.f; s[3] = 0.f; }
        else               { s[0] = 0.f; s[1] = 0.f; s[2] = 0.f; s[3] = 1.f; }
        float* ob = out + b * 400;
        ob[row] = h;

        float nzx = zp[2], nzy = zp[3];
        float nLa = Lp[3], nLb = Lp[4], nLc = Lp[5];

        for (int t = 1; t < 100; t++) {
            float zx = nzx, zy = nzy;
            float La = nLa, Lb = nLb, Lc = nLc;
            if (t < 99) {
                nzx = zp[(t + 1) * 2];  nzy = zp[(t + 1) * 2 + 1];
                nLa = Lp[(t + 1) * 3];  nLb = Lp[(t + 1) * 3 + 1];
                nLc = Lp[(t + 1) * 3 + 2];
            }
            float r00 = La * La, r01 = La * Lb, r11 = Lb * Lb + Lc * Lc;

            float hp = 0.f;
            #pragma unroll
            for (int k = 0; k < 4; k++)
                hp = fmaf(Ar[k], __shfl_sync(0xffffffffu, h, k, 4), hp);

            float tmp[4] = {0.f, 0.f, 0.f, 0.f};
            #pragma unroll
            for (int k = 0; k < 4; k++) {
                #pragma unroll
                for (int j = 0; j < 4; j++)
                    tmp[j] = fmaf(Ar[k], __shfl_sync(0xffffffffu, s[j], k, 4), tmp[j]);
            }
            float sp[4];
            #pragma unroll
            for (int l = 0; l < 4; l++)
                sp[l] = BQ[l] + tmp[0] * A[l * 4] + tmp[1] * A[l * 4 + 1]
                              + tmp[2] * A[l * 4 + 2] + tmp[3] * A[l * 4 + 3];

            float sr0[4], sr1[4];
            #pragma unroll
            for (int l = 0; l < 4; l++) {
                sr0[l] = __shfl_sync(0xffffffffu, sp[l], 0, 4);
                sr1[l] = __shfl_sync(0xffffffffu, sp[l], 1, 4);
            }
            float S00 = sr0[0] + r00, S01 = sr0[1] + r01;
            float S10 = sr1[0] + r01, S11 = sr1[1] + r11;
            float idet = 1.f / (S00 * S11 - S01 * S10);
            float Si00 = S11 * idet, Si01 = -S01 * idet;
            float Si10 = -S10 * idet, Si11 = S00 * idet;
            float K0 = sp[0] * Si00 + sp[1] * Si10;
            float K1 = sp[0] * Si01 + sp[1] * Si11;

            float hp0 = __shfl_sync(0xffffffffu, hp, 0, 4);
            float hp1 = __shfl_sync(0xffffffffu, hp, 1, 4);
            float a0 = zx - hp0, a1 = zy - hp1;
            h = hp + K0 * a0 + K1 * a1;

            #pragma unroll
            for (int l = 0; l < 4; l++)
                s[l] = sp[l] - K0 * sr0[l] - K1 * sr1[l];

            ob[t * 4 + row] = h;
        }
        return;
    }

    // ---- general-C fallback: serial per sequence (8 active lanes) ----
    if (row != 0) return;
    float BQBT[16];
    #pragma unroll
    for (int i = 0; i < 4; i++) {
        float bq0 = Bm[i * 2] * Q[0] + Bm[i * 2 + 1] * Q[2];
        float bq1 = Bm[i * 2] * Q[1] + Bm[i * 2 + 1] * Q[3];
        #pragma unroll
        for (int l = 0; l < 4; l++)
            BQBT[i * 4 + l] = bq0 * Bm[l * 2] + bq1 * Bm[l * 2 + 1];
    }
    const float* zp = g_z + b * 200;
    const float* Lp = g_L + b * 300;
    float h[4] = {zp[0], zp[1], 0.f, 0.f};
    float l0 = Lp[0], l1 = Lp[1], l2 = Lp[2];
    float s[16] = {l0 * l0, l0 * l1, 0.f, 0.f,
                   l0 * l1, l1 * l1 + l2 * l2, 0.f, 0.f,
                   0.f, 0.f, 1.f, 0.f,
                   0.f, 0.f, 0.f, 1.f};
    float* ob = out + b * 400;
    *(float4*)ob = make_float4(h[0], h[1], h[2], h[3]);

    for (int t = 1; t < 100; t++) {
        float zx = zp[t * 2], zy = zp[t * 2 + 1];
        float La = Lp[t * 3], Lb = Lp[t * 3 + 1], Lc = Lp[t * 3 + 2];
        float r00 = La * La, r01 = La * Lb, r11 = Lb * Lb + Lc * Lc;
        float hp[4];
        #pragma unroll
        for (int i = 0; i < 4; i++)
            hp[i] = A[i*4]*h[0] + A[i*4+1]*h[1] + A[i*4+2]*h[2] + A[i*4+3]*h[3];
        float tmp[16];
        #pragma unroll
        for (int i = 0; i < 4; i++)
            #pragma unroll
            for (int k = 0; k < 4; k++)
                tmp[i*4+k] = A[i*4]*s[k] + A[i*4+1]*s[4+k] + A[i*4+2]*s[8+k] + A[i*4+3]*s[12+k];
        float sp[16];
        #pragma unroll
        for (int i = 0; i < 4; i++)
            #pragma unroll
            for (int l = 0; l < 4; l++)
                sp[i*4+l] = BQBT[i*4+l] + tmp[i*4]*A[l*4] + tmp[i*4+1]*A[l*4+1]
                          + tmp[i*4+2]*A[l*4+2] + tmp[i*4+3]*A[l*4+3];
        float sct[8];
        #pragma unroll
        for (int i = 0; i < 4; i++)
            #pragma unroll
            for (int j = 0; j < 2; j++)
                sct[i*2+j] = sp[i*4]*C8[j*4] + sp[i*4+1]*C8[j*4+1]
                           + sp[i*4+2]*C8[j*4+2] + sp[i*4+3]*C8[j*4+3];
        float S00 = C8[0]*sct[0] + C8[1]*sct[2] + C8[2]*sct[4] + C8[3]*sct[6] + r00;
        float S01 = C8[0]*sct[1] + C8[1]*sct[3] + C8[2]*sct[5] + C8[3]*sct[7] + r01;
        float S10 = C8[4]*sct[0] + C8[5]*sct[2] + C8[6]*sct[4] + C8[7]*sct[6] + r01;
        float S11 = C8[4]*sct[1] + C8[5]*sct[3] + C8[6]*sct[5] + C8[7]*sct[7] + r11;
        float idet = 1.f / (S00 * S11 - S01 * S10);
        float Si00 = S11 * idet, Si01 = -S01 * idet, Si10 = -S10 * idet, Si11 = S00 * idet;
        float K[8];
        #pragma unroll
        for (int i = 0; i < 4; i++) {
            K[i*2]   = sct[i*2]*Si00 + sct[i*2+1]*Si10;
            K[i*2+1] = sct[i*2]*Si01 + sct[i*2+1]*Si11;
        }
        float a0 = zx - (C8[0]*hp[0] + C8[1]*hp[1] + C8[2]*hp[2] + C8[3]*hp[3]);
        float a1 = zy - (C8[4]*hp[0] + C8[5]*hp[1] + C8[6]*hp[2] + C8[7]*hp[3]);
        #pragma unroll
        for (int i = 0; i < 4; i++) h[i] = hp[i] + K[i*2]*a0 + K[i*2+1]*a1;
        float M[16];
        #pragma unroll
        for (int i = 0; i < 4; i++)
            #pragma unroll
            for (int j = 0; j < 4; j++)
                M[i*4+j] = (i == j ? 1.f : 0.f) - (K[i*2]*C8[j] + K[i*2+1]*C8[4+j]);
        #pragma unroll
        for (int i = 0; i < 4; i++)
            #pragma unroll
            for (int l = 0; l < 4; l++)
                s[i*4+l] = M[i*4]*sp[l] + M[i*4+1]*sp[4+l]
                         + M[i*4+2]*sp[8+l] + M[i*4+3]*sp[12+l];
        *(float4*)(ob + t * 4) = make_float4(h[0], h[1], h[2], h[3]);
    }
}

extern "C" void kernel_launch(void* const* d_in, const int* in_sizes, int n_in,
                              void* d_out, int out_size) {
    const float* x    = (const float*)d_in[0];
    const float* c1w  = (const float*)d_in[1];
    const float* c1b  = (const float*)d_in[2];
    const float* bn1g = (const float*)d_in[3];
    const float* bn1b = (const float*)d_in[4];
    const float* c2w  = (const float*)d_in[5];
    const float* c2b  = (const float*)d_in[6];
    const float* bn2g = (const float*)d_in[7];
    const float* bn2b = (const float*)d_in[8];
    const float* W1   = (const float*)d_in[9];
    const float* b1   = (const float*)d_in[10];
    const float* W2   = (const float*)d_in[11];
    const float* b2   = (const float*)d_in[12];
    const float* Wz   = (const float*)d_in[13];
    const float* bz   = (const float*)d_in[14];
    const float* WL   = (const float*)d_in[15];
    const float* bL   = (const float*)d_in[16];
    const float* A    = (const float*)d_in[17];
    const float* B    = (const float*)d_in[18];
    const float* C    = (const float*)d_in[19];
    const float* Q    = (const float*)d_in[20];
    float* out = (float*)d_out;

    static int attr_done = 0;
    if (!attr_done) {
        cudaFuncSetAttribute(k_conv1, cudaFuncAttributeMaxDynamicSharedMemorySize, C1_DSM);
        cudaFuncSetAttribute(k_conv2, cudaFuncAttributeMaxDynamicSharedMemorySize, C2_DSM);
        attr_done = 1;
    }

    k_zero<<<1, 32>>>();
    k_pad1<<<1, 32>>>();
    k_pad2<<<1, 32>>>();
    k_conv1<<<dim3(4, 800), 128, C1_DSM>>>(x, c1w, c1b);
    k_conv2<<<100, 224, C2_DSM>>>(c2w, c2b, bn1g, bn1b);
    k_fc<<<100, 256>>>(W1, b1, W2, b2, Wz, bz, WL, bL, bn2g, bn2b);
    k_kf<<<1, 32>>>(A, B, C, Q, out);
}